// round 5
// baseline (speedup 1.0000x reference)
#include <cuda_runtime.h>
#include <cuda_bf16.h>

// NMS: B=32, N=2048, keep first R=100 surviving boxes (greedy, score-desc).
// pred: [B, N, 5] = (score, l, t, r, b);  out: [B, R, 3] = (t, r, b), zero-padded.

#define NMS_N   2048
#define NMS_R   100
#define NT      256
#define EPT     8
#define TARGET  320
#define SEL_CAP 512

typedef unsigned long long ull;

__device__ __forceinline__ unsigned int float_to_ordered(float f) {
    unsigned int u = __float_as_uint(f);
    return (u & 0x80000000u) ? ~u : (u | 0x80000000u);
}
__device__ __forceinline__ ull umin64(ull a, ull b) { return a < b ? a : b; }
__device__ __forceinline__ ull umax64(ull a, ull b) { return a > b ? a : b; }

// suppression test: inter(kb, cb) >= hh (= 0.5 * area(cb)); sentinel kb -> false
__device__ __forceinline__ bool iou_sup(const float4 kb, const float4 cb, float hh) {
    float il = fmaxf(kb.x, cb.x);
    float it = fmaxf(kb.y, cb.y);
    float ir = fminf(kb.z, cb.z);
    float ib = fminf(kb.w, cb.w);
    return fmaxf(0.0f, ir - il) * fmaxf(0.0f, ib - it) >= hh;
}
__device__ __forceinline__ void selset(float4& d, const float4 s, bool p) {
    d.x = p ? s.x : d.x; d.y = p ? s.y : d.y;
    d.z = p ? s.z : d.z; d.w = p ? s.w : d.w;
}

__global__ __launch_bounds__(NT, 1)
void nms_kernel(const float* __restrict__ pred, float* __restrict__ out) {
    // pool (16KB): fast path = selBoxes[512] | selKeys[512] | selHalf[512] | hist[512]
    //              fallback  = fullKeys[2048]
    __shared__ __align__(16) ull pool[2048];
    float4*       selBoxes = (float4*)pool;
    ull*          selKeys  = pool + 1024;
    float*        selHalf  = (float*)(pool + 1536);
    unsigned int* hist     = (unsigned int*)(pool + 1792);
    ull*          fullKeys = pool;

    __shared__ __align__(16) float4 sortedBoxes[SEL_CAP + 4];
    __shared__ float sortedHalf[SEL_CAP + 4];
    __shared__ float keptVals[NMS_R * 3 + 9];   // +9: lane3 slack, pos<NMS_R enforced
    __shared__ int   selCount, thrB, fbFlag, sh_nkept;

    const int b    = blockIdx.x;
    const int tid  = threadIdx.x;
    const int lane = tid & 31;
    const int w    = tid >> 5;
    const float* batch = pred + (size_t)b * NMS_N * 5;

    hist[tid] = 0; hist[tid + 256] = 0;
    if (tid == 0) { selCount = 0; fbFlag = 0; }
    if (tid < 4) { // benign pad entries
        sortedBoxes[SEL_CAP + tid] = make_float4(0.f, 0.f, 0.f, 0.f);
        sortedHalf[SEL_CAP + tid] = 1e30f;
    }
    __syncthreads();

    // ---- Phase 1: scores + histogram (512 buckets over [0,1)) ----
    float sc[EPT];
    int   bk[EPT];
    #pragma unroll
    for (int p = 0; p < EPT; p++) {
        int e = tid + p * NT;
        float s = __ldg(batch + (size_t)e * 5);
        sc[p] = s;
        int bb = (int)(s * 512.0f);
        bb = bb < 0 ? 0 : (bb > 511 ? 511 : bb);
        bk[p] = bb;
        atomicAdd(&hist[bb], 1u);
    }
    __syncthreads();

    // ---- Phase 2: threshold bucket (suffix count >= TARGET), warp 0 ----
    if (w == 0) {
        int base = 512 - 16 * (lane + 1);
        unsigned partial = 0;
        #pragma unroll
        for (int i = 0; i < 16; i++) partial += hist[base + i];
        unsigned cum = partial;
        #pragma unroll
        for (int d = 1; d < 32; d <<= 1) {
            unsigned v = __shfl_up_sync(0xFFFFFFFFu, cum, d);
            if (lane >= d) cum += v;
        }
        unsigned mask = __ballot_sync(0xFFFFFFFFu, cum >= TARGET);
        int fl = __ffs(mask) - 1;
        if (lane == fl) {
            unsigned run = cum - partial;
            int bsel = base;
            for (int bb = base + 15; bb >= base; bb--) {
                run += hist[bb];
                if (run >= TARGET) { bsel = bb; break; }
            }
            thrB = bsel;
        }
    }
    __syncthreads();
    const int B0q = thrB;

    // ---- Phase 3: compact selected; gather boxes ----
    #pragma unroll
    for (int p = 0; p < EPT; p++) {
        if (bk[p] >= B0q) {
            int pos = atomicAdd(&selCount, 1);
            if (pos < SEL_CAP) {
                int e = tid + p * NT;
                const float* pp = batch + (size_t)e * 5;
                float l = __ldg(pp + 1), t = __ldg(pp + 2);
                float r = __ldg(pp + 3), bo = __ldg(pp + 4);
                selBoxes[pos] = make_float4(l, t, r, bo);
                selHalf[pos]  = 0.5f * (r - l) * (bo - t);
                selKeys[pos] = ((ull)(~float_to_ordered(sc[p])) << 21)
                             | ((ull)e << 10) | (unsigned)pos;
            }
        }
    }
    __syncthreads();
    const int nsel = selCount;
    if (nsel > SEL_CAP && tid == 0) fbFlag = 1;
    __syncthreads();

    #define REG_PASS(k, j) do {                                                 \
        if ((j) == 32) {                                                        \
            bool dir = ((xa & (k)) == 0);                                       \
            if ((a > c) == dir) { ull t_ = a; a = c; c = t_; }                  \
        } else {                                                                \
            ull pa = __shfl_xor_sync(0xFFFFFFFFu, a, (j));                      \
            ull pc = __shfl_xor_sync(0xFFFFFFFFu, c, (j));                      \
            bool low = ((lane & (j)) == 0);                                     \
            bool da  = ((xa & (k)) == 0);                                       \
            bool dc  = ((xb & (k)) == 0);                                       \
            a = (low == da) ? umin64(a, pa) : umax64(a, pa);                    \
            c = (low == dc) ? umin64(c, pc) : umax64(c, pc);                    \
        }                                                                       \
    } while (0)

    if (!fbFlag) {
        for (int i = nsel + tid; i < SEL_CAP; i += NT) selKeys[i] = ~(ull)0x3FF;
        __syncthreads();

        // ---- Phase 4: hybrid bitonic sort of 512 keys ----
        const int xa = (w << 6) | lane;
        const int xb = xa + 32;
        ull a = selKeys[xa], c = selKeys[xb];
        #pragma unroll
        for (int k = 2; k <= 64; k <<= 1) {
            #pragma unroll
            for (int j = (k > 32 ? 32 : (k >> 1)); j >= 1; j >>= 1) REG_PASS(k, j);
        }
        #pragma unroll
        for (int k = 128; k <= SEL_CAP; k <<= 1) {
            selKeys[xa] = a; selKeys[xb] = c;
            __syncthreads();
            for (int j = (k >> 1); j >= 64; j >>= 1) {
                unsigned int i  = tid;
                unsigned int lo = ((i & ~(j - 1)) << 1) | (i & (j - 1));
                unsigned int hi = lo | j;
                ull u = selKeys[lo], v = selKeys[hi];
                bool dir = ((lo & k) == 0);
                if ((u > v) == dir) { selKeys[lo] = v; selKeys[hi] = u; }
                __syncthreads();
            }
            a = selKeys[xa]; c = selKeys[xb];
            #pragma unroll
            for (int j = 32; j >= 1; j >>= 1) REG_PASS(k, j);
        }
        // Fused permute: write boxes directly in sorted order
        {
            int sa = (int)(a & 0x3FF), sb = (int)(c & 0x3FF);
            sortedBoxes[xa] = selBoxes[sa]; sortedHalf[xa] = selHalf[sa];
            sortedBoxes[xb] = selBoxes[sb]; sortedHalf[xb] = selHalf[sb];
        }
        __syncthreads();

        // ---- Phase 5: 4-wide branchless greedy (warp 0), tiered slot counts ----
        if (w == 0) {
            const float4 sent = make_float4(1e30f, 1e30f, -1e30f, -1e30f);
            float4 k0s = sent, k1s = sent, k2s = sent, k3s = sent;
            int nkept = 0;
            int cd = 0;

            // lane-distributed pairwise mapping (lanes 0..5)
            const int li = (lane == 0 || lane == 1 || lane == 3) ? 0
                         : (lane == 2 || lane == 4) ? 1 : 2;
            const int lj = (lane == 0) ? 1 : (lane == 1 || lane == 2) ? 2 : 3;

            #define GREEDY_GROUP(NSLOTS)                                          \
            {                                                                     \
                float4 c0 = sortedBoxes[cd],     c1 = sortedBoxes[cd + 1];        \
                float4 c2 = sortedBoxes[cd + 2], c3 = sortedBoxes[cd + 3];        \
                float ha0 = sortedHalf[cd],     ha1 = sortedHalf[cd + 1];         \
                float ha2 = sortedHalf[cd + 2], ha3 = sortedHalf[cd + 3];         \
                unsigned bits = 0;                                                \
                bits |= (iou_sup(k0s, c0, ha0) ? 1u : 0u)                         \
                      | (iou_sup(k0s, c1, ha1) ? 2u : 0u)                         \
                      | (iou_sup(k0s, c2, ha2) ? 4u : 0u)                         \
                      | (iou_sup(k0s, c3, ha3) ? 8u : 0u);                        \
                if (NSLOTS >= 2)                                                  \
                    bits |= (iou_sup(k1s, c0, ha0) ? 1u : 0u)                     \
                          | (iou_sup(k1s, c1, ha1) ? 2u : 0u)                     \
                          | (iou_sup(k1s, c2, ha2) ? 4u : 0u)                     \
                          | (iou_sup(k1s, c3, ha3) ? 8u : 0u);                    \
                if (NSLOTS >= 4) {                                                \
                    bits |= (iou_sup(k2s, c0, ha0) ? 1u : 0u)                     \
                          | (iou_sup(k2s, c1, ha1) ? 2u : 0u)                     \
                          | (iou_sup(k2s, c2, ha2) ? 4u : 0u)                     \
                          | (iou_sup(k2s, c3, ha3) ? 8u : 0u);                    \
                    bits |= (iou_sup(k3s, c0, ha0) ? 1u : 0u)                     \
                          | (iou_sup(k3s, c1, ha1) ? 2u : 0u)                     \
                          | (iou_sup(k3s, c2, ha2) ? 4u : 0u)                     \
                          | (iou_sup(k3s, c3, ha3) ? 8u : 0u);                    \
                }                                                                 \
                /* pairwise: lanes 0..5 each test one (i,j) pair */               \
                {                                                                 \
                    float4 ci = (li == 0) ? c0 : (li == 1) ? c1 : c2;             \
                    float4 cj = (lj == 1) ? c1 : (lj == 2) ? c2 : c3;             \
                    float  hj = (lj == 1) ? ha1 : (lj == 2) ? ha2 : ha3;          \
                    bool ov = iou_sup(ci, cj, hj);                                \
                    if (lane < 6 && ov) bits |= (1u << (4 + lane));               \
                }                                                                 \
                unsigned all = __reduce_or_sync(0xFFFFFFFFu, bits);               \
                bool v0 = cd < nsel, v1 = cd + 1 < nsel;                          \
                bool v2 = cd + 2 < nsel, v3 = cd + 3 < nsel;                      \
                bool k0 = v0 && !(all & 1u);                                      \
                bool k1 = v1 && !(all & 2u) && !(k0 && (all & 16u));              \
                bool k2 = v2 && !(all & 4u) && !(k0 && (all & 32u))               \
                                            && !(k1 && (all & 64u));              \
                bool k3 = v3 && !(all & 8u) && !(k0 && (all & 128u))              \
                                            && !(k1 && (all & 256u))              \
                                            && !(k2 && (all & 512u));             \
                int pos0 = nkept;                                                 \
                int pos1 = pos0 + (k0 ? 1 : 0);                                   \
                int pos2 = pos1 + (k1 ? 1 : 0);                                   \
                int pos3 = pos2 + (k2 ? 1 : 0);                                   \
                nkept    = pos3 + (k3 ? 1 : 0);                                   \
                bool m0 = k0 && ((pos0 & 31) == lane);                            \
                bool m1 = k1 && ((pos1 & 31) == lane);                            \
                bool m2 = k2 && ((pos2 & 31) == lane);                            \
                bool m3 = k3 && ((pos3 & 31) == lane);                            \
                bool anym = m0 | m1 | m2 | m3;                                    \
                float4 nv;                                                        \
                nv.x = m0 ? c0.x : m1 ? c1.x : m2 ? c2.x : c3.x;                  \
                nv.y = m0 ? c0.y : m1 ? c1.y : m2 ? c2.y : c3.y;                  \
                nv.z = m0 ? c0.z : m1 ? c1.z : m2 ? c2.z : c3.z;                  \
                nv.w = m0 ? c0.w : m1 ? c1.w : m2 ? c2.w : c3.w;                  \
                int posx = m0 ? pos0 : m1 ? pos1 : m2 ? pos2 : pos3;              \
                int sl = posx >> 5;                                               \
                selset(k0s, nv, anym && sl == 0);                                 \
                selset(k1s, nv, anym && sl == 1);                                 \
                selset(k2s, nv, anym && sl == 2);                                 \
                selset(k3s, nv, anym && sl == 3);                                 \
                if (lane == 0 && k0 && pos0 < NMS_R) {                            \
                    keptVals[pos0 * 3 + 0] = c0.y;                                \
                    keptVals[pos0 * 3 + 1] = c0.z;                                \
                    keptVals[pos0 * 3 + 2] = c0.w;                                \
                }                                                                 \
                if (lane == 1 && k1 && pos1 < NMS_R) {                            \
                    keptVals[pos1 * 3 + 0] = c1.y;                                \
                    keptVals[pos1 * 3 + 1] = c1.z;                                \
                    keptVals[pos1 * 3 + 2] = c1.w;                                \
                }                                                                 \
                if (lane == 2 && k2 && pos2 < NMS_R) {                            \
                    keptVals[pos2 * 3 + 0] = c2.y;                                \
                    keptVals[pos2 * 3 + 1] = c2.z;                                \
                    keptVals[pos2 * 3 + 2] = c2.w;                                \
                }                                                                 \
                if (lane == 3 && k3 && pos3 < NMS_R) {                            \
                    keptVals[pos3 * 3 + 0] = c3.y;                                \
                    keptVals[pos3 * 3 + 1] = c3.z;                                \
                    keptVals[pos3 * 3 + 2] = c3.w;                                \
                }                                                                 \
                cd += 4;                                                          \
            }

            while (cd < nsel && nkept < NMS_R && nkept <= 32) GREEDY_GROUP(1);
            while (cd < nsel && nkept < NMS_R && nkept <= 64) GREEDY_GROUP(2);
            while (cd < nsel && nkept < NMS_R)                GREEDY_GROUP(4);

            if (lane == 0) sh_nkept = (nkept < NMS_R) ? nkept : NMS_R;
        }
        __syncthreads();
        if (tid == 0 && sh_nkept < NMS_R) fbFlag = 1;
        __syncthreads();
    }

    // ---- Fallback: full 2048 sort + greedy (exact, rarely taken) ----
    if (fbFlag) {
        #pragma unroll
        for (int p = 0; p < EPT; p++) {
            int e = tid + p * NT;
            fullKeys[e] = ((ull)(~float_to_ordered(sc[p])) << 32) | (unsigned)e;
        }
        __syncthreads();
        for (unsigned int k = 2; k <= NMS_N; k <<= 1) {
            for (unsigned int j = k >> 1; j > 0; j >>= 1) {
                #pragma unroll
                for (int p = 0; p < 4; p++) {
                    unsigned int i  = tid + p * NT;
                    unsigned int lo = ((i & ~(j - 1)) << 1) | (i & (j - 1));
                    unsigned int hi = lo | j;
                    ull u = fullKeys[lo], v = fullKeys[hi];
                    bool dir = ((lo & k) == 0);
                    if ((u > v) == dir) { fullKeys[lo] = v; fullKeys[hi] = u; }
                }
                __syncthreads();
            }
        }
        if (w == 0) {
            const float4 sent = make_float4(1e30f, 1e30f, -1e30f, -1e30f);
            float4 k0s = sent, k1s = sent, k2s = sent, k3s = sent;
            int nkept = 0;
            int idx_n = (int)(fullKeys[0] & 0x7FF);
            const float* pn = batch + (size_t)idx_n * 5;
            float l_n = __ldg(pn + 1), t_n = __ldg(pn + 2), r_n = __ldg(pn + 3), b_n = __ldg(pn + 4);
            for (int cd = 0; cd < NMS_N && nkept < NMS_R; ++cd) {
                float4 cb = make_float4(l_n, t_n, r_n, b_n);
                if (cd + 1 < NMS_N) {
                    idx_n = (int)(fullKeys[cd + 1] & 0x7FF);
                    const float* p2 = batch + (size_t)idx_n * 5;
                    l_n = __ldg(p2 + 1); t_n = __ldg(p2 + 2); r_n = __ldg(p2 + 3); b_n = __ldg(p2 + 4);
                }
                float hh = 0.5f * (cb.z - cb.x) * (cb.w - cb.y);
                bool sup = iou_sup(k0s, cb, hh) | iou_sup(k1s, cb, hh)
                         | iou_sup(k2s, cb, hh) | iou_sup(k3s, cb, hh);
                unsigned bal = __ballot_sync(0xFFFFFFFFu, sup);
                bool keep = (bal == 0u);
                bool m = keep && ((nkept & 31) == lane);
                int  sl = nkept >> 5;
                selset(k0s, cb, m && sl == 0);
                selset(k1s, cb, m && sl == 1);
                selset(k2s, cb, m && sl == 2);
                selset(k3s, cb, m && sl == 3);
                if (keep && lane == 0) {
                    keptVals[nkept * 3 + 0] = cb.y;
                    keptVals[nkept * 3 + 1] = cb.z;
                    keptVals[nkept * 3 + 2] = cb.w;
                }
                nkept += keep ? 1 : 0;
            }
            if (lane == 0) sh_nkept = nkept;
        }
        __syncthreads();
    }

    // ---- Output: [R,3], zero-padded ----
    int nk = sh_nkept;
    for (int o = tid; o < NMS_R * 3; o += NT) {
        int slot = o / 3;
        out[(size_t)b * NMS_R * 3 + o] = (slot < nk) ? keptVals[o] : 0.0f;
    }
}

extern "C" void kernel_launch(void* const* d_in, const int* in_sizes, int n_in,
                              void* d_out, int out_size) {
    const float* pred = (const float*)d_in[0];
    float* out = (float*)d_out;
    nms_kernel<<<32, NT>>>(pred, out);
}

// round 6
// speedup vs baseline: 1.0920x; 1.0920x over previous
#include <cuda_runtime.h>
#include <cuda_bf16.h>

// NMS: B=32, N=2048, keep first R=100 surviving boxes (greedy, score-desc).
// pred: [B, N, 5] = (score, l, t, r, b);  out: [B, R, 3] = (t, r, b), zero-padded.

#define NMS_N   2048
#define NMS_R   100
#define NT      256
#define TARGET  320
#define SEL_CAP 512

typedef unsigned long long ull;

__device__ __forceinline__ unsigned int float_to_ordered(float f) {
    unsigned int u = __float_as_uint(f);
    return (u & 0x80000000u) ? ~u : (u | 0x80000000u);
}
__device__ __forceinline__ ull umin64(ull a, ull b) { return a < b ? a : b; }
__device__ __forceinline__ ull umax64(ull a, ull b) { return a > b ? a : b; }

// suppression test: inter(kb, cb) >= hh (= 0.5 * area(cb)); sentinel kb -> false
__device__ __forceinline__ bool iou_sup(const float4 kb, const float4 cb, float hh) {
    float il = fmaxf(kb.x, cb.x);
    float it = fmaxf(kb.y, cb.y);
    float ir = fminf(kb.z, cb.z);
    float ib = fminf(kb.w, cb.w);
    return fmaxf(0.0f, ir - il) * fmaxf(0.0f, ib - it) >= hh;
}
__device__ __forceinline__ void selset(float4& d, const float4 s, bool p) {
    d.x = p ? s.x : d.x; d.y = p ? s.y : d.y;
    d.z = p ? s.z : d.z; d.w = p ? s.w : d.w;
}

__global__ __launch_bounds__(NT, 1)
void nms_kernel(const float* __restrict__ pred, float* __restrict__ out) {
    // pool (16KB): fast path = selBoxes[512] | selKeys[512] | selHalf[512] | hist[512]
    //              fallback  = fullKeys[2048]
    __shared__ __align__(16) ull pool[2048];
    float4*       selBoxes = (float4*)pool;
    ull*          selKeys  = pool + 1024;
    float*        selHalf  = (float*)(pool + 1536);
    unsigned int* hist     = (unsigned int*)(pool + 1792);
    ull*          fullKeys = pool;

    __shared__ __align__(16) float4 sortedBoxes[SEL_CAP];
    __shared__ float sortedHalf[SEL_CAP];
    __shared__ float keptVals[NMS_R * 3];
    __shared__ int   selCount, thrB, fbFlag, sh_nkept;

    const int b    = blockIdx.x;
    const int tid  = threadIdx.x;
    const int lane = tid & 31;
    const int w    = tid >> 5;
    const float* batch = pred + (size_t)b * NMS_N * 5;

    hist[tid] = 0; hist[tid + 256] = 0;
    if (tid == 0) { selCount = 0; fbFlag = 0; }
    __syncthreads();

    // ---- Phase 1: vectorized load (pairs of boxes), histogram ----
    // pair p covers elements e0 = 2*tid + 512*p and e1 = e0+1.
    float  s0v[4], s1v[4];
    float4 box0[4], box1[4];
    int    bk0[4], bk1[4];
    #pragma unroll
    for (int p = 0; p < 4; p++) {
        const float2* src = (const float2*)(batch + (size_t)10 * tid + 2560 * p);
        float2 d0 = __ldg(src + 0);   // (score0, l0)
        float2 d1 = __ldg(src + 1);   // (t0, r0)
        float2 d2 = __ldg(src + 2);   // (b0, score1)
        float2 d3 = __ldg(src + 3);   // (l1, t1)
        float2 d4 = __ldg(src + 4);   // (r1, b1)
        s0v[p] = d0.x;  box0[p] = make_float4(d0.y, d1.x, d1.y, d2.x);
        s1v[p] = d2.y;  box1[p] = make_float4(d3.x, d3.y, d4.x, d4.y);
        int bb0 = (int)(d0.x * 512.0f); bb0 = bb0 < 0 ? 0 : (bb0 > 511 ? 511 : bb0);
        int bb1 = (int)(d2.y * 512.0f); bb1 = bb1 < 0 ? 0 : (bb1 > 511 ? 511 : bb1);
        bk0[p] = bb0; bk1[p] = bb1;
        atomicAdd(&hist[bb0], 1u);
        atomicAdd(&hist[bb1], 1u);
    }
    __syncthreads();

    // ---- Phase 2: threshold bucket (suffix count >= TARGET), warp 0 ----
    if (w == 0) {
        int base = 512 - 16 * (lane + 1);
        unsigned partial = 0;
        #pragma unroll
        for (int i = 0; i < 16; i++) partial += hist[base + i];
        unsigned cum = partial;
        #pragma unroll
        for (int d = 1; d < 32; d <<= 1) {
            unsigned v = __shfl_up_sync(0xFFFFFFFFu, cum, d);
            if (lane >= d) cum += v;
        }
        unsigned mask = __ballot_sync(0xFFFFFFFFu, cum >= TARGET);
        int fl = __ffs(mask) - 1;
        if (lane == fl) {
            unsigned run = cum - partial;
            int bsel = base;
            for (int bb = base + 15; bb >= base; bb--) {
                run += hist[bb];
                if (run >= TARGET) { bsel = bb; break; }
            }
            thrB = bsel;
        }
    }
    __syncthreads();
    const int B0q = thrB;

    // ---- Phase 3: warp-aggregated compaction; boxes written from registers ----
    #pragma unroll
    for (int p = 0; p < 4; p++) {
        #pragma unroll
        for (int i = 0; i < 2; i++) {
            bool  sel = (i == 0 ? bk0[p] : bk1[p]) >= B0q;
            unsigned m = __ballot_sync(0xFFFFFFFFu, sel);
            int cnt = __popc(m);
            int basep = 0;
            int leader = __ffs(m) - 1;
            if (cnt > 0 && lane == leader) basep = atomicAdd(&selCount, cnt);
            basep = __shfl_sync(0xFFFFFFFFu, basep, leader < 0 ? 0 : leader);
            if (sel) {
                int pos = basep + __popc(m & ((1u << lane) - 1u));
                if (pos < SEL_CAP) {
                    float4 bx = (i == 0) ? box0[p] : box1[p];
                    float  s  = (i == 0) ? s0v[p]  : s1v[p];
                    int    e  = 2 * tid + 512 * p + i;
                    selBoxes[pos] = bx;
                    selHalf[pos]  = 0.5f * (bx.z - bx.x) * (bx.w - bx.y);
                    selKeys[pos]  = ((ull)(~float_to_ordered(s)) << 21)
                                  | ((ull)e << 10) | (unsigned)pos;
                }
            }
        }
    }
    __syncthreads();
    const int nsel = selCount;
    if (nsel > SEL_CAP && tid == 0) fbFlag = 1;
    __syncthreads();

    #define REG_PASS(k, j) do {                                                 \
        if ((j) == 32) {                                                        \
            bool dir = ((xa & (k)) == 0);                                       \
            if ((a > c) == dir) { ull t_ = a; a = c; c = t_; }                  \
        } else {                                                                \
            ull pa = __shfl_xor_sync(0xFFFFFFFFu, a, (j));                      \
            ull pc = __shfl_xor_sync(0xFFFFFFFFu, c, (j));                      \
            bool low = ((lane & (j)) == 0);                                     \
            bool da  = ((xa & (k)) == 0);                                       \
            bool dc  = ((xb & (k)) == 0);                                       \
            a = (low == da) ? umin64(a, pa) : umax64(a, pa);                    \
            c = (low == dc) ? umin64(c, pc) : umax64(c, pc);                    \
        }                                                                       \
    } while (0)

    if (!fbFlag) {
        for (int i = nsel + tid; i < SEL_CAP; i += NT) selKeys[i] = ~(ull)0x3FF;
        __syncthreads();

        // ---- Phase 4: hybrid bitonic sort of 512 keys ----
        const int xa = (w << 6) | lane;
        const int xb = xa + 32;
        ull a = selKeys[xa], c = selKeys[xb];
        #pragma unroll
        for (int k = 2; k <= 64; k <<= 1) {
            #pragma unroll
            for (int j = (k > 32 ? 32 : (k >> 1)); j >= 1; j >>= 1) REG_PASS(k, j);
        }
        #pragma unroll
        for (int k = 128; k <= SEL_CAP; k <<= 1) {
            selKeys[xa] = a; selKeys[xb] = c;
            __syncthreads();
            for (int j = (k >> 1); j >= 64; j >>= 1) {
                unsigned int i  = tid;
                unsigned int lo = ((i & ~(j - 1)) << 1) | (i & (j - 1));
                unsigned int hi = lo | j;
                ull u = selKeys[lo], v = selKeys[hi];
                bool dir = ((lo & k) == 0);
                if ((u > v) == dir) { selKeys[lo] = v; selKeys[hi] = u; }
                __syncthreads();
            }
            a = selKeys[xa]; c = selKeys[xb];
            #pragma unroll
            for (int j = 32; j >= 1; j >>= 1) REG_PASS(k, j);
        }
        // Fused permute: write boxes directly in sorted order
        {
            int sa = (int)(a & 0x3FF), sb = (int)(c & 0x3FF);
            sortedBoxes[xa] = selBoxes[sa]; sortedHalf[xa] = selHalf[sa];
            sortedBoxes[xb] = selBoxes[sb]; sortedHalf[xb] = selHalf[sb];
        }
        __syncthreads();

        // ---- Phase 5: branchless dual-candidate greedy (warp 0) ----
        if (w == 0) {
            const float4 sent = make_float4(1e30f, 1e30f, -1e30f, -1e30f);
            float4 k0s = sent, k1s = sent, k2s = sent, k3s = sent;
            int nkept = 0;

            float4 b0 = sortedBoxes[0], b1 = sortedBoxes[1];
            float  h0 = sortedHalf[0],  h1 = sortedHalf[1];

            for (int cd = 0; cd < nsel && nkept < NMS_R; cd += 2) {
                float4 c0 = b0, c1 = b1;
                float  ha0 = h0, ha1 = h1;
                int p2 = (cd + 2) & (SEL_CAP - 1), p3 = (cd + 3) & (SEL_CAP - 1);
                b0 = sortedBoxes[p2]; h0 = sortedHalf[p2];
                b1 = sortedBoxes[p3]; h1 = sortedHalf[p3];

                bool s0 = iou_sup(k0s, c0, ha0) | iou_sup(k1s, c0, ha0)
                        | iou_sup(k2s, c0, ha0) | iou_sup(k3s, c0, ha0);
                bool s1 = iou_sup(k0s, c1, ha1) | iou_sup(k1s, c1, ha1)
                        | iou_sup(k2s, c1, ha1) | iou_sup(k3s, c1, ha1);

                unsigned bal0 = __ballot_sync(0xFFFFFFFFu, s0);
                unsigned bal1 = __ballot_sync(0xFFFFFFFFu, s1);

                bool keep0 = (bal0 == 0u);
                float il = fmaxf(c0.x, c1.x), it = fmaxf(c0.y, c1.y);
                float ir = fminf(c0.z, c1.z), ib = fminf(c0.w, c1.w);
                float pin = fmaxf(0.0f, ir - il) * fmaxf(0.0f, ib - it);
                bool keep1 = (cd + 1 < nsel) && (bal1 == 0u) && !(keep0 && (pin >= ha1));

                int pos0 = nkept;
                int pos1 = nkept + (keep0 ? 1 : 0);

                bool m0 = keep0 && ((pos0 & 31) == lane);
                int  sl0 = pos0 >> 5;
                selset(k0s, c0, m0 && sl0 == 0);
                selset(k1s, c0, m0 && sl0 == 1);
                selset(k2s, c0, m0 && sl0 == 2);
                selset(k3s, c0, m0 && sl0 == 3);

                bool m1 = keep1 && ((pos1 & 31) == lane) && (pos1 < 128);
                int  sl1 = pos1 >> 5;
                selset(k0s, c1, m1 && sl1 == 0);
                selset(k1s, c1, m1 && sl1 == 1);
                selset(k2s, c1, m1 && sl1 == 2);
                selset(k3s, c1, m1 && sl1 == 3);

                if (keep0 && lane == 0) {
                    keptVals[pos0 * 3 + 0] = c0.y;
                    keptVals[pos0 * 3 + 1] = c0.z;
                    keptVals[pos0 * 3 + 2] = c0.w;
                }
                if (keep1 && lane == 1 && pos1 < NMS_R) {
                    keptVals[pos1 * 3 + 0] = c1.y;
                    keptVals[pos1 * 3 + 1] = c1.z;
                    keptVals[pos1 * 3 + 2] = c1.w;
                }
                nkept = pos1 + (keep1 ? 1 : 0);
            }
            if (lane == 0) sh_nkept = (nkept < NMS_R) ? nkept : NMS_R;
        }
        __syncthreads();
        if (tid == 0 && sh_nkept < NMS_R) fbFlag = 1;
        __syncthreads();
    }

    // ---- Fallback: full 2048 sort + greedy (exact, rarely taken) ----
    if (fbFlag) {
        #pragma unroll
        for (int p = 0; p < 4; p++) {
            int e0 = 2 * tid + 512 * p;
            fullKeys[e0]     = ((ull)(~float_to_ordered(s0v[p])) << 32) | (unsigned)e0;
            fullKeys[e0 + 1] = ((ull)(~float_to_ordered(s1v[p])) << 32) | (unsigned)(e0 + 1);
        }
        __syncthreads();
        for (unsigned int k = 2; k <= NMS_N; k <<= 1) {
            for (unsigned int j = k >> 1; j > 0; j >>= 1) {
                #pragma unroll
                for (int p = 0; p < 4; p++) {
                    unsigned int i  = tid + p * NT;
                    unsigned int lo = ((i & ~(j - 1)) << 1) | (i & (j - 1));
                    unsigned int hi = lo | j;
                    ull u = fullKeys[lo], v = fullKeys[hi];
                    bool dir = ((lo & k) == 0);
                    if ((u > v) == dir) { fullKeys[lo] = v; fullKeys[hi] = u; }
                }
                __syncthreads();
            }
        }
        if (w == 0) {
            const float4 sent = make_float4(1e30f, 1e30f, -1e30f, -1e30f);
            float4 k0s = sent, k1s = sent, k2s = sent, k3s = sent;
            int nkept = 0;
            int idx_n = (int)(fullKeys[0] & 0x7FF);
            const float* pn = batch + (size_t)idx_n * 5;
            float l_n = __ldg(pn + 1), t_n = __ldg(pn + 2), r_n = __ldg(pn + 3), b_n = __ldg(pn + 4);
            for (int cd = 0; cd < NMS_N && nkept < NMS_R; ++cd) {
                float4 cb = make_float4(l_n, t_n, r_n, b_n);
                if (cd + 1 < NMS_N) {
                    idx_n = (int)(fullKeys[cd + 1] & 0x7FF);
                    const float* p2 = batch + (size_t)idx_n * 5;
                    l_n = __ldg(p2 + 1); t_n = __ldg(p2 + 2); r_n = __ldg(p2 + 3); b_n = __ldg(p2 + 4);
                }
                float hh = 0.5f * (cb.z - cb.x) * (cb.w - cb.y);
                bool sup = iou_sup(k0s, cb, hh) | iou_sup(k1s, cb, hh)
                         | iou_sup(k2s, cb, hh) | iou_sup(k3s, cb, hh);
                unsigned bal = __ballot_sync(0xFFFFFFFFu, sup);
                bool keep = (bal == 0u);
                bool m = keep && ((nkept & 31) == lane);
                int  sl = nkept >> 5;
                selset(k0s, cb, m && sl == 0);
                selset(k1s, cb, m && sl == 1);
                selset(k2s, cb, m && sl == 2);
                selset(k3s, cb, m && sl == 3);
                if (keep && lane == 0) {
                    keptVals[nkept * 3 + 0] = cb.y;
                    keptVals[nkept * 3 + 1] = cb.z;
                    keptVals[nkept * 3 + 2] = cb.w;
                }
                nkept += keep ? 1 : 0;
            }
            if (lane == 0) sh_nkept = nkept;
        }
        __syncthreads();
    }

    // ---- Output: [R,3], zero-padded ----
    int nk = sh_nkept;
    for (int o = tid; o < NMS_R * 3; o += NT) {
        int slot = o / 3;
        out[(size_t)b * NMS_R * 3 + o] = (slot < nk) ? keptVals[o] : 0.0f;
    }
}

extern "C" void kernel_launch(void* const* d_in, const int* in_sizes, int n_in,
                              void* d_out, int out_size) {
    const float* pred = (const float*)d_in[0];
    float* out = (float*)d_out;
    nms_kernel<<<32, NT>>>(pred, out);
}

// round 7
// speedup vs baseline: 1.2111x; 1.1090x over previous
#include <cuda_runtime.h>
#include <cuda_bf16.h>

// NMS: B=32, N=2048, keep first R=100 surviving boxes (greedy, score-desc).
// pred: [B, N, 5] = (score, l, t, r, b);  out: [B, R, 3] = (t, r, b), zero-padded.

#define NMS_N   2048
#define NMS_R   100
#define NT      256
#define TARGET  320
#define SEL_CAP 512

typedef unsigned long long ull;

__device__ __forceinline__ unsigned int float_to_ordered(float f) {
    unsigned int u = __float_as_uint(f);
    return (u & 0x80000000u) ? ~u : (u | 0x80000000u);
}
__device__ __forceinline__ ull umin64(ull a, ull b) { return a < b ? a : b; }
__device__ __forceinline__ ull umax64(ull a, ull b) { return a > b ? a : b; }

// suppression test: inter(kb, cb) >= hh (= 0.5 * area(cb)); sentinel kb -> false
__device__ __forceinline__ bool iou_sup(const float4 kb, const float4 cb, float hh) {
    float il = fmaxf(kb.x, cb.x);
    float it = fmaxf(kb.y, cb.y);
    float ir = fminf(kb.z, cb.z);
    float ib = fminf(kb.w, cb.w);
    return fmaxf(0.0f, ir - il) * fmaxf(0.0f, ib - it) >= hh;
}
__device__ __forceinline__ void selset(float4& d, const float4 s, bool p) {
    d.x = p ? s.x : d.x; d.y = p ? s.y : d.y;
    d.z = p ? s.z : d.z; d.w = p ? s.w : d.w;
}

__global__ __launch_bounds__(NT, 1)
void nms_kernel(const float* __restrict__ pred, float* __restrict__ out) {
    // pool (16KB): fast path = selBoxes[512] | selKeys[512] | selHalf[512] | hist[512]
    //              fallback  = fullKeys[2048]
    __shared__ __align__(16) ull pool[2048];
    float4*       selBoxes = (float4*)pool;
    ull*          selKeys  = pool + 1024;
    float*        selHalf  = (float*)(pool + 1536);
    unsigned int* hist     = (unsigned int*)(pool + 1792);
    ull*          fullKeys = pool;

    __shared__ __align__(16) float4 sortedBoxes[SEL_CAP];
    __shared__ float sortedHalf[SEL_CAP];
    __shared__ __align__(16) float4 keptBoxes[136];   // kept list (fast path)
    __shared__ float keptVals[NMS_R * 3];
    __shared__ int   selCount, thrB, fbFlag, sh_nkept;

    const int b    = blockIdx.x;
    const int tid  = threadIdx.x;
    const int lane = tid & 31;
    const int w    = tid >> 5;
    const float* batch = pred + (size_t)b * NMS_N * 5;

    hist[tid] = 0; hist[tid + 256] = 0;
    if (tid == 0) { selCount = 0; fbFlag = 0; }
    __syncthreads();

    // ---- Phase 1: vectorized load (pairs of boxes), histogram ----
    float  s0v[4], s1v[4];
    float4 box0[4], box1[4];
    int    bk0[4], bk1[4];
    #pragma unroll
    for (int p = 0; p < 4; p++) {
        const float2* src = (const float2*)(batch + (size_t)10 * tid + 2560 * p);
        float2 d0 = __ldg(src + 0);   // (score0, l0)
        float2 d1 = __ldg(src + 1);   // (t0, r0)
        float2 d2 = __ldg(src + 2);   // (b0, score1)
        float2 d3 = __ldg(src + 3);   // (l1, t1)
        float2 d4 = __ldg(src + 4);   // (r1, b1)
        s0v[p] = d0.x;  box0[p] = make_float4(d0.y, d1.x, d1.y, d2.x);
        s1v[p] = d2.y;  box1[p] = make_float4(d3.x, d3.y, d4.x, d4.y);
        int bb0 = (int)(d0.x * 512.0f); bb0 = bb0 < 0 ? 0 : (bb0 > 511 ? 511 : bb0);
        int bb1 = (int)(d2.y * 512.0f); bb1 = bb1 < 0 ? 0 : (bb1 > 511 ? 511 : bb1);
        bk0[p] = bb0; bk1[p] = bb1;
        atomicAdd(&hist[bb0], 1u);
        atomicAdd(&hist[bb1], 1u);
    }
    __syncthreads();

    // ---- Phase 2: threshold bucket (suffix count >= TARGET), warp 0 ----
    if (w == 0) {
        int base = 512 - 16 * (lane + 1);
        unsigned partial = 0;
        #pragma unroll
        for (int i = 0; i < 16; i++) partial += hist[base + i];
        unsigned cum = partial;
        #pragma unroll
        for (int d = 1; d < 32; d <<= 1) {
            unsigned v = __shfl_up_sync(0xFFFFFFFFu, cum, d);
            if (lane >= d) cum += v;
        }
        unsigned mask = __ballot_sync(0xFFFFFFFFu, cum >= TARGET);
        int fl = __ffs(mask) - 1;
        if (lane == fl) {
            unsigned run = cum - partial;
            int bsel = base;
            for (int bb = base + 15; bb >= base; bb--) {
                run += hist[bb];
                if (run >= TARGET) { bsel = bb; break; }
            }
            thrB = bsel;
        }
    }
    __syncthreads();
    const int B0q = thrB;

    // ---- Phase 3: warp-aggregated compaction; boxes written from registers ----
    #pragma unroll
    for (int p = 0; p < 4; p++) {
        #pragma unroll
        for (int i = 0; i < 2; i++) {
            bool  sel = (i == 0 ? bk0[p] : bk1[p]) >= B0q;
            unsigned m = __ballot_sync(0xFFFFFFFFu, sel);
            int cnt = __popc(m);
            int basep = 0;
            int leader = __ffs(m) - 1;
            if (cnt > 0 && lane == leader) basep = atomicAdd(&selCount, cnt);
            basep = __shfl_sync(0xFFFFFFFFu, basep, leader < 0 ? 0 : leader);
            if (sel) {
                int pos = basep + __popc(m & ((1u << lane) - 1u));
                if (pos < SEL_CAP) {
                    float4 bx = (i == 0) ? box0[p] : box1[p];
                    float  s  = (i == 0) ? s0v[p]  : s1v[p];
                    int    e  = 2 * tid + 512 * p + i;
                    selBoxes[pos] = bx;
                    selHalf[pos]  = 0.5f * (bx.z - bx.x) * (bx.w - bx.y);
                    selKeys[pos]  = ((ull)(~float_to_ordered(s)) << 21)
                                  | ((ull)e << 10) | (unsigned)pos;
                }
            }
        }
    }
    __syncthreads();
    const int nsel = selCount;
    if (nsel > SEL_CAP && tid == 0) fbFlag = 1;
    __syncthreads();

    #define REG_PASS(k, j) do {                                                 \
        if ((j) == 32) {                                                        \
            bool dir = ((xa & (k)) == 0);                                       \
            if ((a > c) == dir) { ull t_ = a; a = c; c = t_; }                  \
        } else {                                                                \
            ull pa = __shfl_xor_sync(0xFFFFFFFFu, a, (j));                      \
            ull pc = __shfl_xor_sync(0xFFFFFFFFu, c, (j));                      \
            bool low = ((lane & (j)) == 0);                                     \
            bool da  = ((xa & (k)) == 0);                                       \
            bool dc  = ((xb & (k)) == 0);                                       \
            a = (low == da) ? umin64(a, pa) : umax64(a, pa);                    \
            c = (low == dc) ? umin64(c, pc) : umax64(c, pc);                    \
        }                                                                       \
    } while (0)

    if (!fbFlag) {
        for (int i = nsel + tid; i < SEL_CAP; i += NT) selKeys[i] = ~(ull)0x3FF;
        __syncthreads();

        // ---- Phase 4: hybrid bitonic sort of 512 keys ----
        const int xa = (w << 6) | lane;
        const int xb = xa + 32;
        ull a = selKeys[xa], c = selKeys[xb];
        #pragma unroll
        for (int k = 2; k <= 64; k <<= 1) {
            #pragma unroll
            for (int j = (k > 32 ? 32 : (k >> 1)); j >= 1; j >>= 1) REG_PASS(k, j);
        }
        #pragma unroll
        for (int k = 128; k <= SEL_CAP; k <<= 1) {
            selKeys[xa] = a; selKeys[xb] = c;
            __syncthreads();
            for (int j = (k >> 1); j >= 64; j >>= 1) {
                unsigned int i  = tid;
                unsigned int lo = ((i & ~(j - 1)) << 1) | (i & (j - 1));
                unsigned int hi = lo | j;
                ull u = selKeys[lo], v = selKeys[hi];
                bool dir = ((lo & k) == 0);
                if ((u > v) == dir) { selKeys[lo] = v; selKeys[hi] = u; }
                __syncthreads();
            }
            a = selKeys[xa]; c = selKeys[xb];
            #pragma unroll
            for (int j = 32; j >= 1; j >>= 1) REG_PASS(k, j);
        }
        // Fused permute: write boxes directly in sorted order
        {
            int sa = (int)(a & 0x3FF), sb = (int)(c & 0x3FF);
            sortedBoxes[xa] = selBoxes[sa]; sortedHalf[xa] = selHalf[sa];
            sortedBoxes[xb] = selBoxes[sb]; sortedHalf[xb] = selHalf[sb];
        }
        __syncthreads();

        // ---- Phase 5: warp-parallel block greedy (warp 0), 32 candidates/step ----
        if (w == 0) {
            int nkept = 0;
            int cd = 0;
            const unsigned FULL = 0xFFFFFFFFu;
            const unsigned below = (lane == 31) ? 0x7FFFFFFFu : ((1u << lane) - 1u);

            while (cd < nsel && nkept < NMS_R) {
                int ci = cd + lane;
                bool valid = ci < nsel;
                int cidx = ci & (SEL_CAP - 1);
                float4 cb = sortedBoxes[cidx];
                float  hh = sortedHalf[cidx];

                // 1) suppressed by previously-kept boxes (broadcast reads)
                bool supk = false;
                for (int kj = 0; kj < nkept; kj++)
                    supk |= iou_sup(keptBoxes[kj], cb, hh);

                // 2) supBy mask: in-block candidates j that suppress me (j != lane)
                unsigned supBy = 0;
                #pragma unroll 8
                for (int j = 0; j < 32; j++) {
                    int jj = (cd + j) & (SEL_CAP - 1);
                    float4 ob = sortedBoxes[jj];
                    if (iou_sup(ob, cb, hh)) supBy |= (1u << j);
                }
                supBy &= ~(1u << lane);

                // 3) greedy fixpoint: K_i = valid_i && !supk_i && no kept j<i suppresses i
                unsigned base = __ballot_sync(FULL, valid && !supk);
                unsigned K = base;
                #pragma unroll 1
                for (int it = 0; it < 32; it++) {
                    bool alive = ((base >> lane) & 1u) && ((supBy & K & below) == 0u);
                    unsigned Kn = __ballot_sync(FULL, alive);
                    if (Kn == K) break;
                    K = Kn;
                }

                // 4) parallel insertion
                bool kept = (K >> lane) & 1u;
                int  pos  = nkept + __popc(K & below);
                if (kept && pos < 136) keptBoxes[pos] = cb;
                if (kept && pos < NMS_R) {
                    keptVals[pos * 3 + 0] = cb.y;
                    keptVals[pos * 3 + 1] = cb.z;
                    keptVals[pos * 3 + 2] = cb.w;
                }
                __syncwarp();
                nkept += __popc(K);
                cd += 32;
            }
            if (lane == 0) sh_nkept = (nkept < NMS_R) ? nkept : NMS_R;
        }
        __syncthreads();
        if (tid == 0 && sh_nkept < NMS_R) fbFlag = 1;
        __syncthreads();
    }

    // ---- Fallback: full 2048 sort + greedy (exact, rarely taken) ----
    if (fbFlag) {
        const float4 sent = make_float4(1e30f, 1e30f, -1e30f, -1e30f);
        #pragma unroll
        for (int p = 0; p < 4; p++) {
            int e0 = 2 * tid + 512 * p;
            fullKeys[e0]     = ((ull)(~float_to_ordered(s0v[p])) << 32) | (unsigned)e0;
            fullKeys[e0 + 1] = ((ull)(~float_to_ordered(s1v[p])) << 32) | (unsigned)(e0 + 1);
        }
        __syncthreads();
        for (unsigned int k = 2; k <= NMS_N; k <<= 1) {
            for (unsigned int j = k >> 1; j > 0; j >>= 1) {
                #pragma unroll
                for (int p = 0; p < 4; p++) {
                    unsigned int i  = tid + p * NT;
                    unsigned int lo = ((i & ~(j - 1)) << 1) | (i & (j - 1));
                    unsigned int hi = lo | j;
                    ull u = fullKeys[lo], v = fullKeys[hi];
                    bool dir = ((lo & k) == 0);
                    if ((u > v) == dir) { fullKeys[lo] = v; fullKeys[hi] = u; }
                }
                __syncthreads();
            }
        }
        if (w == 0) {
            float4 k0s = sent, k1s = sent, k2s = sent, k3s = sent;
            int nkept = 0;
            int idx_n = (int)(fullKeys[0] & 0x7FF);
            const float* pn = batch + (size_t)idx_n * 5;
            float l_n = __ldg(pn + 1), t_n = __ldg(pn + 2), r_n = __ldg(pn + 3), b_n = __ldg(pn + 4);
            for (int cd = 0; cd < NMS_N && nkept < NMS_R; ++cd) {
                float4 cb = make_float4(l_n, t_n, r_n, b_n);
                if (cd + 1 < NMS_N) {
                    idx_n = (int)(fullKeys[cd + 1] & 0x7FF);
                    const float* p2 = batch + (size_t)idx_n * 5;
                    l_n = __ldg(p2 + 1); t_n = __ldg(p2 + 2); r_n = __ldg(p2 + 3); b_n = __ldg(p2 + 4);
                }
                float hh = 0.5f * (cb.z - cb.x) * (cb.w - cb.y);
                bool sup = iou_sup(k0s, cb, hh) | iou_sup(k1s, cb, hh)
                         | iou_sup(k2s, cb, hh) | iou_sup(k3s, cb, hh);
                unsigned bal = __ballot_sync(0xFFFFFFFFu, sup);
                bool keep = (bal == 0u);
                bool m = keep && ((nkept & 31) == lane);
                int  sl = nkept >> 5;
                selset(k0s, cb, m && sl == 0);
                selset(k1s, cb, m && sl == 1);
                selset(k2s, cb, m && sl == 2);
                selset(k3s, cb, m && sl == 3);
                if (keep && lane == 0) {
                    keptVals[nkept * 3 + 0] = cb.y;
                    keptVals[nkept * 3 + 1] = cb.z;
                    keptVals[nkept * 3 + 2] = cb.w;
                }
                nkept += keep ? 1 : 0;
            }
            if (lane == 0) sh_nkept = nkept;
        }
        __syncthreads();
    }

    // ---- Output: [R,3], zero-padded ----
    int nk = sh_nkept;
    for (int o = tid; o < NMS_R * 3; o += NT) {
        int slot = o / 3;
        out[(size_t)b * NMS_R * 3 + o] = (slot < nk) ? keptVals[o] : 0.0f;
    }
}

extern "C" void kernel_launch(void* const* d_in, const int* in_sizes, int n_in,
                              void* d_out, int out_size) {
    const float* pred = (const float*)d_in[0];
    float* out = (float*)d_out;
    nms_kernel<<<32, NT>>>(pred, out);
}

// round 8
// speedup vs baseline: 1.5487x; 1.2788x over previous
#include <cuda_runtime.h>
#include <cuda_bf16.h>

// NMS: B=32, N=2048, keep first R=100 surviving boxes (greedy, score-desc).
// pred: [B, N, 5] = (score, l, t, r, b);  out: [B, R, 3] = (t, r, b), zero-padded.

#define NMS_N      2048
#define NMS_R      100
#define NT         256
#define TARGET     200
#define SEL_CAP    256
#define MAT_N      192
#define MAT_STRIDE 7

typedef unsigned long long ull;

__device__ __forceinline__ unsigned int float_to_ordered(float f) {
    unsigned int u = __float_as_uint(f);
    return (u & 0x80000000u) ? ~u : (u | 0x80000000u);
}
__device__ __forceinline__ ull umin64(ull a, ull b) { return a < b ? a : b; }
__device__ __forceinline__ ull umax64(ull a, ull b) { return a > b ? a : b; }

// suppress cb if inter(kb, cb) >= hh (= 0.5 * area(cb)); sentinel kb -> false
__device__ __forceinline__ bool iou_sup(const float4 kb, const float4 cb, float hh) {
    float il = fmaxf(kb.x, cb.x);
    float it = fmaxf(kb.y, cb.y);
    float ir = fminf(kb.z, cb.z);
    float ib = fminf(kb.w, cb.w);
    return fmaxf(0.0f, ir - il) * fmaxf(0.0f, ib - it) >= hh;
}
__device__ __forceinline__ void selset(float4& d, const float4 s, bool p) {
    d.x = p ? s.x : d.x; d.y = p ? s.y : d.y;
    d.z = p ? s.z : d.z; d.w = p ? s.w : d.w;
}

__global__ __launch_bounds__(NT, 1)
void nms_kernel(const float* __restrict__ pred, float* __restrict__ out) {
    // 16KB pool, aliased across phases:
    //   select/sort: selBoxes[256] (4KB) | selKeys[256] (2KB) | selHalf[256] (1KB) | hist[512] (2KB)
    //   greedy     : supMat[192*7] (5.25KB, overlays dead selBoxes)
    //   fallback   : fullKeys[2048] (16KB)
    __shared__ __align__(16) ull pool[2048];
    float4*       selBoxes = (float4*)pool;                 // [256]
    ull*          selKeys  = pool + 512;                    // [256]
    float*        selHalf  = (float*)(pool + 768);          // [256]
    unsigned int* hist     = (unsigned int*)(pool + 896);   // [512]
    ull*          fullKeys = pool;
    unsigned int* supMat   = (unsigned int*)pool;           // [192*7]

    __shared__ __align__(16) float4 sortedBoxes[SEL_CAP];
    __shared__ float sortedHalf[SEL_CAP];
    __shared__ __align__(16) float4 keptBoxes[136];
    __shared__ float keptVals[NMS_R * 3];
    __shared__ int   selCount, thrB, fbFlag, sh_nkept;

    const int b    = blockIdx.x;
    const int tid  = threadIdx.x;
    const int lane = tid & 31;
    const int w    = tid >> 5;
    const unsigned FULL = 0xFFFFFFFFu;
    const float* batch = pred + (size_t)b * NMS_N * 5;

    hist[tid] = 0; hist[tid + 256] = 0;
    if (tid == 0) { selCount = 0; fbFlag = 0; }
    __syncthreads();

    // ---- Phase 1: vectorized load (pairs of boxes), histogram ----
    float  s0v[4], s1v[4];
    float4 box0[4], box1[4];
    int    bk0[4], bk1[4];
    #pragma unroll
    for (int p = 0; p < 4; p++) {
        const float2* src = (const float2*)(batch + (size_t)10 * tid + 2560 * p);
        float2 d0 = __ldg(src + 0);   // (score0, l0)
        float2 d1 = __ldg(src + 1);   // (t0, r0)
        float2 d2 = __ldg(src + 2);   // (b0, score1)
        float2 d3 = __ldg(src + 3);   // (l1, t1)
        float2 d4 = __ldg(src + 4);   // (r1, b1)
        s0v[p] = d0.x;  box0[p] = make_float4(d0.y, d1.x, d1.y, d2.x);
        s1v[p] = d2.y;  box1[p] = make_float4(d3.x, d3.y, d4.x, d4.y);
        int bb0 = (int)(d0.x * 512.0f); bb0 = bb0 < 0 ? 0 : (bb0 > 511 ? 511 : bb0);
        int bb1 = (int)(d2.y * 512.0f); bb1 = bb1 < 0 ? 0 : (bb1 > 511 ? 511 : bb1);
        bk0[p] = bb0; bk1[p] = bb1;
        atomicAdd(&hist[bb0], 1u);
        atomicAdd(&hist[bb1], 1u);
    }
    __syncthreads();

    // ---- Phase 2: threshold bucket (suffix count >= TARGET), warp 0 ----
    if (w == 0) {
        int base = 512 - 16 * (lane + 1);
        unsigned partial = 0;
        #pragma unroll
        for (int i = 0; i < 16; i++) partial += hist[base + i];
        unsigned cum = partial;
        #pragma unroll
        for (int d = 1; d < 32; d <<= 1) {
            unsigned v = __shfl_up_sync(FULL, cum, d);
            if (lane >= d) cum += v;
        }
        unsigned mask = __ballot_sync(FULL, cum >= TARGET);
        int fl = __ffs(mask) - 1;
        if (lane == fl) {
            unsigned run = cum - partial;
            int bsel = base;
            for (int bb = base + 15; bb >= base; bb--) {
                run += hist[bb];
                if (run >= TARGET) { bsel = bb; break; }
            }
            thrB = bsel;
        }
    }
    __syncthreads();
    const int B0q = thrB;

    // ---- Phase 3: warp-aggregated compaction; boxes written from registers ----
    #pragma unroll
    for (int p = 0; p < 4; p++) {
        #pragma unroll
        for (int i = 0; i < 2; i++) {
            bool  sel = (i == 0 ? bk0[p] : bk1[p]) >= B0q;
            unsigned m = __ballot_sync(FULL, sel);
            int cnt = __popc(m);
            int basep = 0;
            int leader = __ffs(m) - 1;
            if (cnt > 0 && lane == leader) basep = atomicAdd(&selCount, cnt);
            basep = __shfl_sync(FULL, basep, leader < 0 ? 0 : leader);
            if (sel) {
                int pos = basep + __popc(m & ((1u << lane) - 1u));
                if (pos < SEL_CAP) {
                    float4 bx = (i == 0) ? box0[p] : box1[p];
                    float  s  = (i == 0) ? s0v[p]  : s1v[p];
                    int    e  = 2 * tid + 512 * p + i;
                    selBoxes[pos] = bx;
                    selHalf[pos]  = 0.5f * (bx.z - bx.x) * (bx.w - bx.y);
                    selKeys[pos]  = ((ull)(~float_to_ordered(s)) << 21)
                                  | ((ull)e << 10) | (unsigned)pos;
                }
            }
        }
    }
    __syncthreads();
    const int nsel = selCount;
    if (nsel > SEL_CAP && tid == 0) fbFlag = 1;
    __syncthreads();

    #define REG_PASS(k, j) do {                                                 \
        if ((j) == 32) {                                                        \
            bool dir = ((xa & (k)) == 0);                                       \
            if ((a > c) == dir) { ull t_ = a; a = c; c = t_; }                  \
        } else {                                                                \
            ull pa = __shfl_xor_sync(FULL, a, (j));                             \
            ull pc = __shfl_xor_sync(FULL, c, (j));                             \
            bool low = ((lane & (j)) == 0);                                     \
            bool da  = ((xa & (k)) == 0);                                       \
            bool dc  = ((xb & (k)) == 0);                                       \
            a = (low == da) ? umin64(a, pa) : umax64(a, pa);                    \
            c = (low == dc) ? umin64(c, pc) : umax64(c, pc);                    \
        }                                                                       \
    } while (0)

    if (!fbFlag) {
        for (int i = nsel + tid; i < SEL_CAP; i += NT) selKeys[i] = ~(ull)0x3FF;
        __syncthreads();

        // ---- Phase 4: hybrid bitonic sort of 256 keys (warps 0-3, 2 regs/thread) ----
        const int xa = (w << 6) | lane;
        const int xb = xa + 32;
        ull a = 0, c = 0;
        if (w < 4) {
            a = selKeys[xa]; c = selKeys[xb];
            #pragma unroll
            for (int k = 2; k <= 64; k <<= 1) {
                #pragma unroll
                for (int j = (k > 32 ? 32 : (k >> 1)); j >= 1; j >>= 1) REG_PASS(k, j);
            }
        }
        #pragma unroll
        for (int k = 128; k <= SEL_CAP; k <<= 1) {
            if (w < 4) { selKeys[xa] = a; selKeys[xb] = c; }
            __syncthreads();
            for (int j = (k >> 1); j >= 64; j >>= 1) {
                if (tid < SEL_CAP / 2) {
                    unsigned int i  = tid;
                    unsigned int lo = ((i & ~(j - 1)) << 1) | (i & (j - 1));
                    unsigned int hi = lo | j;
                    ull u = selKeys[lo], v = selKeys[hi];
                    bool dir = ((lo & k) == 0);
                    if ((u > v) == dir) { selKeys[lo] = v; selKeys[hi] = u; }
                }
                __syncthreads();
            }
            if (w < 4) {
                a = selKeys[xa]; c = selKeys[xb];
                #pragma unroll
                for (int j = 32; j >= 1; j >>= 1) REG_PASS(k, j);
            }
        }
        // Fused permute: write boxes directly in sorted order (pad slots -> box 0, benign)
        if (w < 4) {
            int sa = (int)(a & 0x3FF) & (SEL_CAP - 1), sb = (int)(c & 0x3FF) & (SEL_CAP - 1);
            sortedBoxes[xa] = selBoxes[sa]; sortedHalf[xa] = selHalf[sa];
            sortedBoxes[xb] = selBoxes[sb]; sortedHalf[xb] = selHalf[sb];
        }
        __syncthreads();

        // ---- Phase 4c: parallel triangular suppression matrix (warps 0-5) ----
        if (tid < MAT_N) {
            float4 cb = sortedBoxes[tid];
            float  hh = sortedHalf[tid];
            #pragma unroll
            for (int w2 = 0; w2 < 6; w2++) {
                unsigned mm = 0;
                int jbase = w2 << 5;
                int jend = tid - jbase; if (jend > 32) jend = 32;
                for (int jo = 0; jo < jend; jo++) {
                    if (iou_sup(sortedBoxes[jbase + jo], cb, hh)) mm |= 1u << jo;
                }
                supMat[tid * MAT_STRIDE + w2] = mm;
            }
        }
        __syncthreads();

        // ---- Phase 5: bitwise greedy resolution (warp 0) ----
        if (w == 0) {
            unsigned KM0 = 0, KM1 = 0, KM2 = 0, KM3 = 0, KM4 = 0, KM5 = 0;
            int nkept = 0;
            const unsigned below = (1u << lane) - 1u;
            int matLim = nsel < MAT_N ? nsel : MAT_N;
            int nblk = (matLim + 31) >> 5;

            for (int blk = 0; blk < nblk && nkept < NMS_R; blk++) {
                int i = (blk << 5) + lane;
                bool valid = i < matLim;
                const unsigned* row = supMat + i * MAT_STRIDE;
                unsigned m0 = row[0], m1 = row[1], m2 = row[2];
                unsigned m3 = row[3], m4 = row[4], m5 = row[5];
                unsigned sk = (m0 & KM0) | (m1 & KM1) | (m2 & KM2)
                            | (m3 & KM3) | (m4 & KM4) | (m5 & KM5);
                unsigned inb = blk == 0 ? m0 : blk == 1 ? m1 : blk == 2 ? m2
                             : blk == 3 ? m3 : blk == 4 ? m4 : m5;
                unsigned base = __ballot_sync(FULL, valid && sk == 0u);
                unsigned K = base;
                #pragma unroll 1
                for (int it = 0; it < 32; it++) {
                    bool alive = ((base >> lane) & 1u) && ((inb & K) == 0u);
                    unsigned Kn = __ballot_sync(FULL, alive);
                    if (Kn == K) break;
                    K = Kn;
                }
                bool kept = (K >> lane) & 1u;
                int  pos  = nkept + __popc(K & below);
                float4 cb = sortedBoxes[i];
                if (kept) keptBoxes[pos] = cb;
                if (kept && pos < NMS_R) {
                    keptVals[pos * 3 + 0] = cb.y;
                    keptVals[pos * 3 + 1] = cb.z;
                    keptVals[pos * 3 + 2] = cb.w;
                }
                KM0 |= (blk == 0) ? K : 0u; KM1 |= (blk == 1) ? K : 0u;
                KM2 |= (blk == 2) ? K : 0u; KM3 |= (blk == 3) ? K : 0u;
                KM4 |= (blk == 4) ? K : 0u; KM5 |= (blk == 5) ? K : 0u;
                nkept += __popc(K);
            }

            // Continuation beyond MAT_N (rare): R7-style warp-parallel blocks
            int cd = MAT_N;
            while (cd < nsel && nkept < NMS_R) {
                int ci = cd + lane;
                bool valid = ci < nsel;
                int cidx = ci & (SEL_CAP - 1);
                float4 cb = sortedBoxes[cidx];
                float  hh = sortedHalf[cidx];
                bool supk = false;
                for (int kj = 0; kj < nkept; kj++)
                    supk |= iou_sup(keptBoxes[kj], cb, hh);
                unsigned supBy = 0;
                #pragma unroll 8
                for (int j = 0; j < 32; j++) {
                    int jj = (cd + j) & (SEL_CAP - 1);
                    float4 ob = sortedBoxes[jj];
                    if (iou_sup(ob, cb, hh)) supBy |= (1u << j);
                }
                supBy &= ~(1u << lane);
                unsigned base = __ballot_sync(FULL, valid && !supk);
                unsigned K = base;
                #pragma unroll 1
                for (int it = 0; it < 32; it++) {
                    bool alive = ((base >> lane) & 1u) && ((supBy & K & below) == 0u);
                    unsigned Kn = __ballot_sync(FULL, alive);
                    if (Kn == K) break;
                    K = Kn;
                }
                bool kept = (K >> lane) & 1u;
                int  pos  = nkept + __popc(K & below);
                if (kept && pos < 136) keptBoxes[pos] = cb;
                if (kept && pos < NMS_R) {
                    keptVals[pos * 3 + 0] = cb.y;
                    keptVals[pos * 3 + 1] = cb.z;
                    keptVals[pos * 3 + 2] = cb.w;
                }
                __syncwarp();
                nkept += __popc(K);
                cd += 32;
            }
            if (lane == 0) sh_nkept = (nkept < NMS_R) ? nkept : NMS_R;
        }
        __syncthreads();
        if (tid == 0 && sh_nkept < NMS_R) fbFlag = 1;
        __syncthreads();
    }

    // ---- Fallback: full 2048 sort + greedy (exact, rarely taken) ----
    if (fbFlag) {
        const float4 sent = make_float4(1e30f, 1e30f, -1e30f, -1e30f);
        #pragma unroll
        for (int p = 0; p < 4; p++) {
            int e0 = 2 * tid + 512 * p;
            fullKeys[e0]     = ((ull)(~float_to_ordered(s0v[p])) << 32) | (unsigned)e0;
            fullKeys[e0 + 1] = ((ull)(~float_to_ordered(s1v[p])) << 32) | (unsigned)(e0 + 1);
        }
        __syncthreads();
        for (unsigned int k = 2; k <= NMS_N; k <<= 1) {
            for (unsigned int j = k >> 1; j > 0; j >>= 1) {
                #pragma unroll
                for (int p = 0; p < 4; p++) {
                    unsigned int i  = tid + p * NT;
                    unsigned int lo = ((i & ~(j - 1)) << 1) | (i & (j - 1));
                    unsigned int hi = lo | j;
                    ull u = fullKeys[lo], v = fullKeys[hi];
                    bool dir = ((lo & k) == 0);
                    if ((u > v) == dir) { fullKeys[lo] = v; fullKeys[hi] = u; }
                }
                __syncthreads();
            }
        }
        if (w == 0) {
            float4 k0s = sent, k1s = sent, k2s = sent, k3s = sent;
            int nkept = 0;
            int idx_n = (int)(fullKeys[0] & 0x7FF);
            const float* pn = batch + (size_t)idx_n * 5;
            float l_n = __ldg(pn + 1), t_n = __ldg(pn + 2), r_n = __ldg(pn + 3), b_n = __ldg(pn + 4);
            for (int cd = 0; cd < NMS_N && nkept < NMS_R; ++cd) {
                float4 cb = make_float4(l_n, t_n, r_n, b_n);
                if (cd + 1 < NMS_N) {
                    idx_n = (int)(fullKeys[cd + 1] & 0x7FF);
                    const float* p2 = batch + (size_t)idx_n * 5;
                    l_n = __ldg(p2 + 1); t_n = __ldg(p2 + 2); r_n = __ldg(p2 + 3); b_n = __ldg(p2 + 4);
                }
                float hh = 0.5f * (cb.z - cb.x) * (cb.w - cb.y);
                bool sup = iou_sup(k0s, cb, hh) | iou_sup(k1s, cb, hh)
                         | iou_sup(k2s, cb, hh) | iou_sup(k3s, cb, hh);
                unsigned bal = __ballot_sync(FULL, sup);
                bool keep = (bal == 0u);
                bool m = keep && ((nkept & 31) == lane);
                int  sl = nkept >> 5;
                selset(k0s, cb, m && sl == 0);
                selset(k1s, cb, m && sl == 1);
                selset(k2s, cb, m && sl == 2);
                selset(k3s, cb, m && sl == 3);
                if (keep && lane == 0) {
                    keptVals[nkept * 3 + 0] = cb.y;
                    keptVals[nkept * 3 + 1] = cb.z;
                    keptVals[nkept * 3 + 2] = cb.w;
                }
                nkept += keep ? 1 : 0;
            }
            if (lane == 0) sh_nkept = nkept;
        }
        __syncthreads();
    }

    // ---- Output: [R,3], zero-padded ----
    int nk = sh_nkept;
    for (int o = tid; o < NMS_R * 3; o += NT) {
        int slot = o / 3;
        out[(size_t)b * NMS_R * 3 + o] = (slot < nk) ? keptVals[o] : 0.0f;
    }
}

extern "C" void kernel_launch(void* const* d_in, const int* in_sizes, int n_in,
                              void* d_out, int out_size) {
    const float* pred = (const float*)d_in[0];
    float* out = (float*)d_out;
    nms_kernel<<<32, NT>>>(pred, out);
}

// round 9
// speedup vs baseline: 1.6667x; 1.0762x over previous
#include <cuda_runtime.h>
#include <cuda_bf16.h>

// NMS: B=32, N=2048, keep first R=100 surviving boxes (greedy, score-desc).
// pred: [B, N, 5] = (score, l, t, r, b);  out: [B, R, 3] = (t, r, b), zero-padded.

#define NMS_N      2048
#define NMS_R      100
#define NT         256
#define SEL_CAP    256
#define MAT_N      192
#define MAT_STRIDE 7
#define T_SEL      0.90f

typedef unsigned long long ull;

__device__ __forceinline__ unsigned int float_to_ordered(float f) {
    unsigned int u = __float_as_uint(f);
    return (u & 0x80000000u) ? ~u : (u | 0x80000000u);
}
__device__ __forceinline__ ull umin64(ull a, ull b) { return a < b ? a : b; }
__device__ __forceinline__ ull umax64(ull a, ull b) { return a > b ? a : b; }

// suppress cb if inter(kb, cb) >= hh (= 0.5 * area(cb)); sentinel kb -> false
__device__ __forceinline__ bool iou_sup(const float4 kb, const float4 cb, float hh) {
    float il = fmaxf(kb.x, cb.x);
    float it = fmaxf(kb.y, cb.y);
    float ir = fminf(kb.z, cb.z);
    float ib = fminf(kb.w, cb.w);
    return fmaxf(0.0f, ir - il) * fmaxf(0.0f, ib - it) >= hh;
}
__device__ __forceinline__ void selset(float4& d, const float4 s, bool p) {
    d.x = p ? s.x : d.x; d.y = p ? s.y : d.y;
    d.z = p ? s.z : d.z; d.w = p ? s.w : d.w;
}

__global__ __launch_bounds__(NT, 1)
void nms_kernel(const float* __restrict__ pred, float* __restrict__ out) {
    // 16KB pool, aliased across phases:
    //   select/sort: selBoxes[256] (4KB) | selKeys[256] (2KB) | selHalf[256] (1KB)
    //   greedy     : supMat[192*7] (5.25KB, overlays dead selBoxes)
    //   fallback   : fullKeys[2048] (16KB)
    __shared__ __align__(16) ull pool[2048];
    float4*       selBoxes = (float4*)pool;                 // [256]
    ull*          selKeys  = pool + 512;                    // [256]
    float*        selHalf  = (float*)(pool + 768);          // [256]
    ull*          fullKeys = pool;
    unsigned int* supMat   = (unsigned int*)pool;           // [192*7]

    __shared__ __align__(16) float4 sortedBoxes[SEL_CAP];
    __shared__ float sortedHalf[SEL_CAP];
    __shared__ __align__(16) float4 keptBoxes[136];
    __shared__ float keptVals[NMS_R * 3];
    __shared__ int   selCount, fbFlag, sh_nkept;

    const int b    = blockIdx.x;
    const int tid  = threadIdx.x;
    const int lane = tid & 31;
    const int w    = tid >> 5;
    const unsigned FULL = 0xFFFFFFFFu;
    const float* batch = pred + (size_t)b * NMS_N * 5;

    if (tid == 0) { selCount = 0; fbFlag = 0; }

    // ---- Phase 1: wide vectorized load; 8 boxes/thread ----
    float  s[8];
    float4 bx[8];
    {
        const float4* src = (const float4*)(batch + (size_t)40 * tid);
        float4 v0 = __ldg(src + 0), v1 = __ldg(src + 1), v2 = __ldg(src + 2);
        float4 v3 = __ldg(src + 3), v4 = __ldg(src + 4), v5 = __ldg(src + 5);
        float4 v6 = __ldg(src + 6), v7 = __ldg(src + 7), v8 = __ldg(src + 8);
        float4 v9 = __ldg(src + 9);
        s[0] = v0.x; bx[0] = make_float4(v0.y, v0.z, v0.w, v1.x);
        s[1] = v1.y; bx[1] = make_float4(v1.z, v1.w, v2.x, v2.y);
        s[2] = v2.z; bx[2] = make_float4(v2.w, v3.x, v3.y, v3.z);
        s[3] = v3.w; bx[3] = make_float4(v4.x, v4.y, v4.z, v4.w);
        s[4] = v5.x; bx[4] = make_float4(v5.y, v5.z, v5.w, v6.x);
        s[5] = v6.y; bx[5] = make_float4(v6.z, v6.w, v7.x, v7.y);
        s[6] = v7.z; bx[6] = make_float4(v7.w, v8.x, v8.y, v8.z);
        s[7] = v8.w; bx[7] = make_float4(v9.x, v9.y, v9.z, v9.w);
    }
    __syncthreads();   // selCount init visible

    // ---- Phase 2: fixed-threshold warp-aggregated compaction ----
    #pragma unroll
    for (int j = 0; j < 8; j++) {
        bool sel = s[j] >= T_SEL;
        unsigned m = __ballot_sync(FULL, sel);
        int cnt = __popc(m);
        int basep = 0;
        int leader = __ffs(m) - 1;
        if (cnt > 0 && lane == leader) basep = atomicAdd(&selCount, cnt);
        basep = __shfl_sync(FULL, basep, leader < 0 ? 0 : leader);
        if (sel) {
            int pos = basep + __popc(m & ((1u << lane) - 1u));
            if (pos < SEL_CAP) {
                int e = 8 * tid + j;
                selBoxes[pos] = bx[j];
                selHalf[pos]  = 0.5f * (bx[j].z - bx[j].x) * (bx[j].w - bx[j].y);
                selKeys[pos]  = ((ull)(~float_to_ordered(s[j])) << 21)
                              | ((ull)e << 10) | (unsigned)pos;
            }
        }
    }
    __syncthreads();
    const int nsel = selCount;
    if (nsel > SEL_CAP && tid == 0) fbFlag = 1;
    __syncthreads();

    #define REG_PASS(k, j) do {                                                 \
        if ((j) == 32) {                                                        \
            bool dir = ((xa & (k)) == 0);                                       \
            if ((a > c) == dir) { ull t_ = a; a = c; c = t_; }                  \
        } else {                                                                \
            ull pa = __shfl_xor_sync(FULL, a, (j));                             \
            ull pc = __shfl_xor_sync(FULL, c, (j));                             \
            bool low = ((lane & (j)) == 0);                                     \
            bool da  = ((xa & (k)) == 0);                                       \
            bool dc  = ((xb & (k)) == 0);                                       \
            a = (low == da) ? umin64(a, pa) : umax64(a, pa);                    \
            c = (low == dc) ? umin64(c, pc) : umax64(c, pc);                    \
        }                                                                       \
    } while (0)

    if (!fbFlag) {
        for (int i = nsel + tid; i < SEL_CAP; i += NT) selKeys[i] = ~(ull)0x3FF;
        __syncthreads();

        // ---- Phase 3: hybrid bitonic sort of 256 keys (warps 0-3, 2 regs/thread) ----
        const int xa = (w << 6) | lane;
        const int xb = xa + 32;
        ull a = 0, c = 0;
        if (w < 4) {
            a = selKeys[xa]; c = selKeys[xb];
            #pragma unroll
            for (int k = 2; k <= 64; k <<= 1) {
                #pragma unroll
                for (int j = (k > 32 ? 32 : (k >> 1)); j >= 1; j >>= 1) REG_PASS(k, j);
            }
        }
        #pragma unroll
        for (int k = 128; k <= SEL_CAP; k <<= 1) {
            if (w < 4) { selKeys[xa] = a; selKeys[xb] = c; }
            __syncthreads();
            for (int j = (k >> 1); j >= 64; j >>= 1) {
                if (tid < SEL_CAP / 2) {
                    unsigned int i  = tid;
                    unsigned int lo = ((i & ~(j - 1)) << 1) | (i & (j - 1));
                    unsigned int hi = lo | j;
                    ull u = selKeys[lo], v = selKeys[hi];
                    bool dir = ((lo & k) == 0);
                    if ((u > v) == dir) { selKeys[lo] = v; selKeys[hi] = u; }
                }
                __syncthreads();
            }
            if (w < 4) {
                a = selKeys[xa]; c = selKeys[xb];
                #pragma unroll
                for (int j = 32; j >= 1; j >>= 1) REG_PASS(k, j);
            }
        }
        // Fused permute: write boxes directly in sorted order (pad slots -> box 0, benign)
        if (w < 4) {
            int sa = (int)(a & 0x3FF) & (SEL_CAP - 1), sb = (int)(c & 0x3FF) & (SEL_CAP - 1);
            sortedBoxes[xa] = selBoxes[sa]; sortedHalf[xa] = selHalf[sa];
            sortedBoxes[xb] = selBoxes[sb]; sortedHalf[xb] = selHalf[sb];
        }
        __syncthreads();

        // ---- Phase 4: balanced triangular suppression matrix (all 8 warps) ----
        // column-major slots: slot = wb*MAT_N + i  -> warp-uniform jend
        for (int slot = tid; slot < MAT_N * 6; slot += NT) {
            int wb = slot / MAT_N;
            int i  = slot - wb * MAT_N;
            int jbase = wb << 5;
            int jend = i - jbase; jend = jend > 32 ? 32 : jend;
            unsigned mm = 0;
            if (jend > 0) {
                float4 cb = sortedBoxes[i];
                float  hh = sortedHalf[i];
                for (int jo = 0; jo < jend; jo++) {
                    if (iou_sup(sortedBoxes[jbase + jo], cb, hh)) mm |= 1u << jo;
                }
            }
            supMat[i * MAT_STRIDE + wb] = mm;
        }
        __syncthreads();

        // ---- Phase 5: bitwise greedy resolution (warp 0) ----
        if (w == 0) {
            unsigned KM0 = 0, KM1 = 0, KM2 = 0, KM3 = 0, KM4 = 0, KM5 = 0;
            int nkept = 0;
            const unsigned below = (1u << lane) - 1u;
            int matLim = nsel < MAT_N ? nsel : MAT_N;
            int nblk = (matLim + 31) >> 5;

            for (int blk = 0; blk < nblk && nkept < NMS_R; blk++) {
                int i = (blk << 5) + lane;
                bool valid = i < matLim;
                const unsigned* row = supMat + i * MAT_STRIDE;
                unsigned m0 = row[0], m1 = row[1], m2 = row[2];
                unsigned m3 = row[3], m4 = row[4], m5 = row[5];
                unsigned sk = (m0 & KM0) | (m1 & KM1) | (m2 & KM2)
                            | (m3 & KM3) | (m4 & KM4) | (m5 & KM5);
                unsigned inb = blk == 0 ? m0 : blk == 1 ? m1 : blk == 2 ? m2
                             : blk == 3 ? m3 : blk == 4 ? m4 : m5;
                unsigned base = __ballot_sync(FULL, valid && sk == 0u);
                unsigned K = base;
                #pragma unroll 1
                for (int it = 0; it < 32; it++) {
                    bool alive = ((base >> lane) & 1u) && ((inb & K) == 0u);
                    unsigned Kn = __ballot_sync(FULL, alive);
                    if (Kn == K) break;
                    K = Kn;
                }
                bool kept = (K >> lane) & 1u;
                int  pos  = nkept + __popc(K & below);
                float4 cb = sortedBoxes[i];
                if (kept) keptBoxes[pos] = cb;
                if (kept && pos < NMS_R) {
                    keptVals[pos * 3 + 0] = cb.y;
                    keptVals[pos * 3 + 1] = cb.z;
                    keptVals[pos * 3 + 2] = cb.w;
                }
                KM0 |= (blk == 0) ? K : 0u; KM1 |= (blk == 1) ? K : 0u;
                KM2 |= (blk == 2) ? K : 0u; KM3 |= (blk == 3) ? K : 0u;
                KM4 |= (blk == 4) ? K : 0u; KM5 |= (blk == 5) ? K : 0u;
                nkept += __popc(K);
            }

            // Continuation beyond MAT_N (rare): warp-parallel blocks
            int cd = MAT_N;
            while (cd < nsel && nkept < NMS_R) {
                int ci = cd + lane;
                bool valid = ci < nsel;
                int cidx = ci & (SEL_CAP - 1);
                float4 cb = sortedBoxes[cidx];
                float  hh = sortedHalf[cidx];
                bool supk = false;
                for (int kj = 0; kj < nkept; kj++)
                    supk |= iou_sup(keptBoxes[kj], cb, hh);
                unsigned supBy = 0;
                #pragma unroll 8
                for (int j = 0; j < 32; j++) {
                    int jj = (cd + j) & (SEL_CAP - 1);
                    float4 ob = sortedBoxes[jj];
                    if (iou_sup(ob, cb, hh)) supBy |= (1u << j);
                }
                supBy &= ~(1u << lane);
                unsigned base = __ballot_sync(FULL, valid && !supk);
                unsigned K = base;
                #pragma unroll 1
                for (int it = 0; it < 32; it++) {
                    bool alive = ((base >> lane) & 1u) && ((supBy & K & below) == 0u);
                    unsigned Kn = __ballot_sync(FULL, alive);
                    if (Kn == K) break;
                    K = Kn;
                }
                bool kept = (K >> lane) & 1u;
                int  pos  = nkept + __popc(K & below);
                if (kept && pos < 136) keptBoxes[pos] = cb;
                if (kept && pos < NMS_R) {
                    keptVals[pos * 3 + 0] = cb.y;
                    keptVals[pos * 3 + 1] = cb.z;
                    keptVals[pos * 3 + 2] = cb.w;
                }
                __syncwarp();
                nkept += __popc(K);
                cd += 32;
            }
            if (lane == 0) sh_nkept = (nkept < NMS_R) ? nkept : NMS_R;
        }
        __syncthreads();
        if (tid == 0 && sh_nkept < NMS_R) fbFlag = 1;
        __syncthreads();
    }

    // ---- Fallback: full 2048 sort + greedy (exact, rarely taken) ----
    if (fbFlag) {
        const float4 sent = make_float4(1e30f, 1e30f, -1e30f, -1e30f);
        #pragma unroll
        for (int j = 0; j < 8; j++) {
            int e = 8 * tid + j;
            fullKeys[e] = ((ull)(~float_to_ordered(s[j])) << 32) | (unsigned)e;
        }
        __syncthreads();
        for (unsigned int k = 2; k <= NMS_N; k <<= 1) {
            for (unsigned int j = k >> 1; j > 0; j >>= 1) {
                #pragma unroll
                for (int p = 0; p < 4; p++) {
                    unsigned int i  = tid + p * NT;
                    unsigned int lo = ((i & ~(j - 1)) << 1) | (i & (j - 1));
                    unsigned int hi = lo | j;
                    ull u = fullKeys[lo], v = fullKeys[hi];
                    bool dir = ((lo & k) == 0);
                    if ((u > v) == dir) { fullKeys[lo] = v; fullKeys[hi] = u; }
                }
                __syncthreads();
            }
        }
        if (w == 0) {
            float4 k0s = sent, k1s = sent, k2s = sent, k3s = sent;
            int nkept = 0;
            int idx_n = (int)(fullKeys[0] & 0x7FF);
            const float* pn = batch + (size_t)idx_n * 5;
            float l_n = __ldg(pn + 1), t_n = __ldg(pn + 2), r_n = __ldg(pn + 3), b_n = __ldg(pn + 4);
            for (int cd = 0; cd < NMS_N && nkept < NMS_R; ++cd) {
                float4 cb = make_float4(l_n, t_n, r_n, b_n);
                if (cd + 1 < NMS_N) {
                    idx_n = (int)(fullKeys[cd + 1] & 0x7FF);
                    const float* p2 = batch + (size_t)idx_n * 5;
                    l_n = __ldg(p2 + 1); t_n = __ldg(p2 + 2); r_n = __ldg(p2 + 3); b_n = __ldg(p2 + 4);
                }
                float hh = 0.5f * (cb.z - cb.x) * (cb.w - cb.y);
                bool sup = iou_sup(k0s, cb, hh) | iou_sup(k1s, cb, hh)
                         | iou_sup(k2s, cb, hh) | iou_sup(k3s, cb, hh);
                unsigned bal = __ballot_sync(FULL, sup);
                bool keep = (bal == 0u);
                bool m = keep && ((nkept & 31) == lane);
                int  sl = nkept >> 5;
                selset(k0s, cb, m && sl == 0);
                selset(k1s, cb, m && sl == 1);
                selset(k2s, cb, m && sl == 2);
                selset(k3s, cb, m && sl == 3);
                if (keep && lane == 0) {
                    keptVals[nkept * 3 + 0] = cb.y;
                    keptVals[nkept * 3 + 1] = cb.z;
                    keptVals[nkept * 3 + 2] = cb.w;
                }
                nkept += keep ? 1 : 0;
            }
            if (lane == 0) sh_nkept = nkept;
        }
        __syncthreads();
    }

    // ---- Output: [R,3], zero-padded ----
    int nk = sh_nkept;
    for (int o = tid; o < NMS_R * 3; o += NT) {
        int slot = o / 3;
        out[(size_t)b * NMS_R * 3 + o] = (slot < nk) ? keptVals[o] : 0.0f;
    }
}

extern "C" void kernel_launch(void* const* d_in, const int* in_sizes, int n_in,
                              void* d_out, int out_size) {
    const float* pred = (const float*)d_in[0];
    float* out = (float*)d_out;
    nms_kernel<<<32, NT>>>(pred, out);
}

// round 10
// speedup vs baseline: 1.8041x; 1.0825x over previous
#include <cuda_runtime.h>
#include <cuda_bf16.h>

// NMS: B=32, N=2048, keep first R=100 surviving boxes (greedy, score-desc).
// pred: [B, N, 5] = (score, l, t, r, b);  out: [B, R, 3] = (t, r, b), zero-padded.

#define NMS_N      2048
#define NMS_R      100
#define NT         256
#define SEL_CAP    256
#define MAT_N      160
#define MAT_COLS   5
#define MAT_STRIDE 7
#define T_SEL      0.90f

typedef unsigned long long ull;

__device__ __forceinline__ unsigned int float_to_ordered(float f) {
    unsigned int u = __float_as_uint(f);
    return (u & 0x80000000u) ? ~u : (u | 0x80000000u);
}
__device__ __forceinline__ ull umin64(ull a, ull b) { return a < b ? a : b; }
__device__ __forceinline__ ull umax64(ull a, ull b) { return a > b ? a : b; }

// suppress cb if inter(kb, cb) >= hh (= 0.5 * area(cb)); sentinel kb -> false
__device__ __forceinline__ bool iou_sup(const float4 kb, const float4 cb, float hh) {
    float il = fmaxf(kb.x, cb.x);
    float it = fmaxf(kb.y, cb.y);
    float ir = fminf(kb.z, cb.z);
    float ib = fminf(kb.w, cb.w);
    return fmaxf(0.0f, ir - il) * fmaxf(0.0f, ib - it) >= hh;
}
__device__ __forceinline__ void selset(float4& d, const float4 s, bool p) {
    d.x = p ? s.x : d.x; d.y = p ? s.y : d.y;
    d.z = p ? s.z : d.z; d.w = p ? s.w : d.w;
}

__global__ __launch_bounds__(NT, 1)
void nms_kernel(const float* __restrict__ pred, float* __restrict__ out) {
    // 16KB pool, aliased across phases:
    //   select/sort: selBoxes[256] (4KB) | selKeys[256] (2KB) | selHalf[256] (1KB)
    //   greedy     : supMat[160*7] (4.4KB, overlays dead selBoxes)
    //   fallback   : fullKeys[2048] (16KB)
    __shared__ __align__(16) ull pool[2048];
    float4*       selBoxes = (float4*)pool;                 // [256]
    ull*          selKeys  = pool + 512;                    // [256]
    float*        selHalf  = (float*)(pool + 768);          // [256]
    ull*          fullKeys = pool;
    unsigned int* supMat   = (unsigned int*)pool;           // [160*7]

    __shared__ __align__(16) float4 sortedBoxes[SEL_CAP];
    __shared__ float sortedHalf[SEL_CAP];
    __shared__ __align__(16) float4 keptBoxes[136];
    __shared__ float keptVals[NMS_R * 3];
    __shared__ int   selCount, sh_nkept;

    const int b    = blockIdx.x;
    const int tid  = threadIdx.x;
    const int lane = tid & 31;
    const int w    = tid >> 5;
    const unsigned FULL = 0xFFFFFFFFu;
    const float* batch = pred + (size_t)b * NMS_N * 5;

    if (tid == 0) selCount = 0;
    selKeys[tid] = ~(ull)0x3FF;   // pre-pad: max key, slot bits 0

    // ---- Phase 1: wide vectorized load; 8 boxes/thread ----
    float  s[8];
    float4 bx[8];
    {
        const float4* src = (const float4*)(batch + (size_t)40 * tid);
        float4 v0 = __ldg(src + 0), v1 = __ldg(src + 1), v2 = __ldg(src + 2);
        float4 v3 = __ldg(src + 3), v4 = __ldg(src + 4), v5 = __ldg(src + 5);
        float4 v6 = __ldg(src + 6), v7 = __ldg(src + 7), v8 = __ldg(src + 8);
        float4 v9 = __ldg(src + 9);
        s[0] = v0.x; bx[0] = make_float4(v0.y, v0.z, v0.w, v1.x);
        s[1] = v1.y; bx[1] = make_float4(v1.z, v1.w, v2.x, v2.y);
        s[2] = v2.z; bx[2] = make_float4(v2.w, v3.x, v3.y, v3.z);
        s[3] = v3.w; bx[3] = make_float4(v4.x, v4.y, v4.z, v4.w);
        s[4] = v5.x; bx[4] = make_float4(v5.y, v5.z, v5.w, v6.x);
        s[5] = v6.y; bx[5] = make_float4(v6.z, v6.w, v7.x, v7.y);
        s[6] = v7.z; bx[6] = make_float4(v7.w, v8.x, v8.y, v8.z);
        s[7] = v8.w; bx[7] = make_float4(v9.x, v9.y, v9.z, v9.w);
    }
    __syncthreads();   // selCount init + key pre-pad visible

    // ---- Phase 2: fixed-threshold warp-aggregated compaction ----
    #pragma unroll
    for (int j = 0; j < 8; j++) {
        bool sel = s[j] >= T_SEL;
        unsigned m = __ballot_sync(FULL, sel);
        int cnt = __popc(m);
        int basep = 0;
        int leader = __ffs(m) - 1;
        if (cnt > 0 && lane == leader) basep = atomicAdd(&selCount, cnt);
        basep = __shfl_sync(FULL, basep, leader < 0 ? 0 : leader);
        if (sel) {
            int pos = basep + __popc(m & ((1u << lane) - 1u));
            if (pos < SEL_CAP) {
                int e = 8 * tid + j;
                selBoxes[pos] = bx[j];
                selHalf[pos]  = 0.5f * (bx[j].z - bx[j].x) * (bx[j].w - bx[j].y);
                selKeys[pos]  = ((ull)(~float_to_ordered(s[j])) << 21)
                              | ((ull)e << 10) | (unsigned)pos;
            }
        }
    }
    __syncthreads();
    const int nsel = selCount;
    const bool fb1 = (nsel > SEL_CAP);   // uniform across block

    #define REG_PASS(k, j) do {                                                 \
        if ((j) == 32) {                                                        \
            bool dir = ((xa & (k)) == 0);                                       \
            if ((a > c) == dir) { ull t_ = a; a = c; c = t_; }                  \
        } else {                                                                \
            ull pa = __shfl_xor_sync(FULL, a, (j));                             \
            ull pc = __shfl_xor_sync(FULL, c, (j));                             \
            bool low = ((lane & (j)) == 0);                                     \
            bool da  = ((xa & (k)) == 0);                                       \
            bool dc  = ((xb & (k)) == 0);                                       \
            a = (low == da) ? umin64(a, pa) : umax64(a, pa);                    \
            c = (low == dc) ? umin64(c, pc) : umax64(c, pc);                    \
        }                                                                       \
    } while (0)

    if (!fb1) {
        // ---- Phase 3: hybrid bitonic sort of 256 keys (warps 0-3, 2 regs/thread) ----
        const int xa = (w << 6) | lane;
        const int xb = xa + 32;
        ull a = 0, c = 0;
        if (w < 4) {
            a = selKeys[xa]; c = selKeys[xb];
            #pragma unroll
            for (int k = 2; k <= 64; k <<= 1) {
                #pragma unroll
                for (int j = (k > 32 ? 32 : (k >> 1)); j >= 1; j >>= 1) REG_PASS(k, j);
            }
        }
        #pragma unroll
        for (int k = 128; k <= SEL_CAP; k <<= 1) {
            if (w < 4) { selKeys[xa] = a; selKeys[xb] = c; }
            __syncthreads();
            for (int j = (k >> 1); j >= 64; j >>= 1) {
                if (tid < SEL_CAP / 2) {
                    unsigned int i  = tid;
                    unsigned int lo = ((i & ~(j - 1)) << 1) | (i & (j - 1));
                    unsigned int hi = lo | j;
                    ull u = selKeys[lo], v = selKeys[hi];
                    bool dir = ((lo & k) == 0);
                    if ((u > v) == dir) { selKeys[lo] = v; selKeys[hi] = u; }
                }
                __syncthreads();
            }
            if (w < 4) {
                a = selKeys[xa]; c = selKeys[xb];
                #pragma unroll
                for (int j = 32; j >= 1; j >>= 1) REG_PASS(k, j);
            }
        }
        // Fused permute: write boxes directly in sorted order (pad slots -> box 0, benign)
        if (w < 4) {
            int sa = (int)(a & 0x3FF) & (SEL_CAP - 1), sb = (int)(c & 0x3FF) & (SEL_CAP - 1);
            sortedBoxes[xa] = selBoxes[sa]; sortedHalf[xa] = selHalf[sa];
            sortedBoxes[xb] = selBoxes[sb]; sortedHalf[xb] = selHalf[sb];
        }
        __syncthreads();

        // ---- Phase 4: balanced triangular suppression matrix (all 8 warps) ----
        // column-major slots: slot = wb*MAT_N + i  -> warp-uniform jend
        for (int slot = tid; slot < MAT_N * MAT_COLS; slot += NT) {
            int wb = slot / MAT_N;
            int i  = slot - wb * MAT_N;
            int jbase = wb << 5;
            int jend = i - jbase; jend = jend > 32 ? 32 : jend;
            unsigned mm = 0;
            if (jend > 0) {
                float4 cb = sortedBoxes[i];
                float  hh = sortedHalf[i];
                for (int jo = 0; jo < jend; jo++) {
                    if (iou_sup(sortedBoxes[jbase + jo], cb, hh)) mm |= 1u << jo;
                }
            }
            supMat[i * MAT_STRIDE + wb] = mm;
        }
        __syncthreads();

        // ---- Phase 5: bitwise greedy resolution (warp 0) ----
        if (w == 0) {
            unsigned KM0 = 0, KM1 = 0, KM2 = 0, KM3 = 0, KM4 = 0;
            int nkept = 0;
            const unsigned below = (1u << lane) - 1u;
            int matLim = nsel < MAT_N ? nsel : MAT_N;
            int nblk = (matLim + 31) >> 5;

            for (int blk = 0; blk < nblk && nkept < NMS_R; blk++) {
                int i = (blk << 5) + lane;
                bool valid = i < matLim;
                const unsigned* row = supMat + i * MAT_STRIDE;
                unsigned m0 = row[0], m1 = row[1], m2 = row[2];
                unsigned m3 = row[3], m4 = row[4];
                unsigned sk = (m0 & KM0) | (m1 & KM1) | (m2 & KM2)
                            | (m3 & KM3) | (m4 & KM4);
                unsigned inb = blk == 0 ? m0 : blk == 1 ? m1 : blk == 2 ? m2
                             : blk == 3 ? m3 : m4;
                unsigned base = __ballot_sync(FULL, valid && sk == 0u);
                unsigned K = base;
                #pragma unroll 1
                for (int it = 0; it < 32; it++) {
                    bool alive = ((base >> lane) & 1u) && ((inb & K) == 0u);
                    unsigned Kn = __ballot_sync(FULL, alive);
                    if (Kn == K) break;
                    K = Kn;
                }
                bool kept = (K >> lane) & 1u;
                int  pos  = nkept + __popc(K & below);
                float4 cb = sortedBoxes[i];
                if (kept) keptBoxes[pos] = cb;
                if (kept && pos < NMS_R) {
                    keptVals[pos * 3 + 0] = cb.y;
                    keptVals[pos * 3 + 1] = cb.z;
                    keptVals[pos * 3 + 2] = cb.w;
                }
                KM0 |= (blk == 0) ? K : 0u; KM1 |= (blk == 1) ? K : 0u;
                KM2 |= (blk == 2) ? K : 0u; KM3 |= (blk == 3) ? K : 0u;
                KM4 |= (blk == 4) ? K : 0u;
                nkept += __popc(K);
            }

            // Continuation beyond MAT_N (rare): warp-parallel blocks
            int cd = MAT_N;
            while (cd < nsel && nkept < NMS_R) {
                int ci = cd + lane;
                bool valid = ci < nsel;
                int cidx = ci & (SEL_CAP - 1);
                float4 cb = sortedBoxes[cidx];
                float  hh = sortedHalf[cidx];
                bool supk = false;
                for (int kj = 0; kj < nkept; kj++)
                    supk |= iou_sup(keptBoxes[kj], cb, hh);
                unsigned supBy = 0;
                #pragma unroll 8
                for (int j = 0; j < 32; j++) {
                    int jj = (cd + j) & (SEL_CAP - 1);
                    float4 ob = sortedBoxes[jj];
                    if (iou_sup(ob, cb, hh)) supBy |= (1u << j);
                }
                supBy &= ~(1u << lane);
                unsigned base = __ballot_sync(FULL, valid && !supk);
                unsigned K = base;
                #pragma unroll 1
                for (int it = 0; it < 32; it++) {
                    bool alive = ((base >> lane) & 1u) && ((supBy & K & below) == 0u);
                    unsigned Kn = __ballot_sync(FULL, alive);
                    if (Kn == K) break;
                    K = Kn;
                }
                bool kept = (K >> lane) & 1u;
                int  pos  = nkept + __popc(K & below);
                if (kept && pos < 136) keptBoxes[pos] = cb;
                if (kept && pos < NMS_R) {
                    keptVals[pos * 3 + 0] = cb.y;
                    keptVals[pos * 3 + 1] = cb.z;
                    keptVals[pos * 3 + 2] = cb.w;
                }
                __syncwarp();
                nkept += __popc(K);
                cd += 32;
            }
            if (lane == 0) sh_nkept = (nkept < NMS_R) ? nkept : NMS_R;
        }
        __syncthreads();
    }

    // fallback condition: overflow OR too few kept (uniform decision)
    const bool fb = fb1 || (sh_nkept < NMS_R);

    // ---- Fallback: full 2048 sort + greedy (exact, rarely taken) ----
    if (fb) {
        const float4 sent = make_float4(1e30f, 1e30f, -1e30f, -1e30f);
        #pragma unroll
        for (int j = 0; j < 8; j++) {
            int e = 8 * tid + j;
            fullKeys[e] = ((ull)(~float_to_ordered(s[j])) << 32) | (unsigned)e;
        }
        __syncthreads();
        for (unsigned int k = 2; k <= NMS_N; k <<= 1) {
            for (unsigned int j = k >> 1; j > 0; j >>= 1) {
                #pragma unroll
                for (int p = 0; p < 4; p++) {
                    unsigned int i  = tid + p * NT;
                    unsigned int lo = ((i & ~(j - 1)) << 1) | (i & (j - 1));
                    unsigned int hi = lo | j;
                    ull u = fullKeys[lo], v = fullKeys[hi];
                    bool dir = ((lo & k) == 0);
                    if ((u > v) == dir) { fullKeys[lo] = v; fullKeys[hi] = u; }
                }
                __syncthreads();
            }
        }
        if (w == 0) {
            float4 k0s = sent, k1s = sent, k2s = sent, k3s = sent;
            int nkept = 0;
            int idx_n = (int)(fullKeys[0] & 0x7FF);
            const float* pn = batch + (size_t)idx_n * 5;
            float l_n = __ldg(pn + 1), t_n = __ldg(pn + 2), r_n = __ldg(pn + 3), b_n = __ldg(pn + 4);
            for (int cd = 0; cd < NMS_N && nkept < NMS_R; ++cd) {
                float4 cb = make_float4(l_n, t_n, r_n, b_n);
                if (cd + 1 < NMS_N) {
                    idx_n = (int)(fullKeys[cd + 1] & 0x7FF);
                    const float* p2 = batch + (size_t)idx_n * 5;
                    l_n = __ldg(p2 + 1); t_n = __ldg(p2 + 2); r_n = __ldg(p2 + 3); b_n = __ldg(p2 + 4);
                }
                float hh = 0.5f * (cb.z - cb.x) * (cb.w - cb.y);
                bool sup = iou_sup(k0s, cb, hh) | iou_sup(k1s, cb, hh)
                         | iou_sup(k2s, cb, hh) | iou_sup(k3s, cb, hh);
                unsigned bal = __ballot_sync(FULL, sup);
                bool keep = (bal == 0u);
                bool m = keep && ((nkept & 31) == lane);
                int  sl = nkept >> 5;
                selset(k0s, cb, m && sl == 0);
                selset(k1s, cb, m && sl == 1);
                selset(k2s, cb, m && sl == 2);
                selset(k3s, cb, m && sl == 3);
                if (keep && lane == 0) {
                    keptVals[nkept * 3 + 0] = cb.y;
                    keptVals[nkept * 3 + 1] = cb.z;
                    keptVals[nkept * 3 + 2] = cb.w;
                }
                nkept += keep ? 1 : 0;
            }
            if (lane == 0) sh_nkept = nkept;
        }
        __syncthreads();
    }

    // ---- Output: [R,3], zero-padded ----
    int nk = sh_nkept;
    for (int o = tid; o < NMS_R * 3; o += NT) {
        int slot = o / 3;
        out[(size_t)b * NMS_R * 3 + o] = (slot < nk) ? keptVals[o] : 0.0f;
    }
}

extern "C" void kernel_launch(void* const* d_in, const int* in_sizes, int n_in,
                              void* d_out, int out_size) {
    const float* pred = (const float*)d_in[0];
    float* out = (float*)d_out;
    nms_kernel<<<32, NT>>>(pred, out);
}